// round 8
// baseline (speedup 1.0000x reference)
#include <cuda_runtime.h>
#include <cuda_bf16.h>
#include <math.h>

#define BB 2
#define LL 2048
#define DD 1024
#define HH 16
#define HDIM 64
#define MROWS (BB*LL)   // 4096

// Scratch (allocation-free per harness rules): Q, K, V, attention output
static __device__ float g_Q[MROWS * DD];
static __device__ float g_K[MROWS * DD];
static __device__ float g_V[MROWS * DD];
static __device__ float g_A[MROWS * DD];
static __device__ int   g_kpm[BB * LL];   // canonical key-padding mask (0/1)

// ---------------------------------------------------------------------------
// Normalize key_padding_mask regardless of on-disk dtype.
// The reference produces jnp.bool_, but the harness only serializes
// float32/int32/bfloat16 — detect which layout we actually got.
//   int32 layout : every 32-bit word is 0 or 1
//   float32 layout: every 32-bit word is 0 or 0x3F800000 (1.0f)
//   otherwise     : treat as packed uint8
// ---------------------------------------------------------------------------
__global__ void normalize_kpm(const int* __restrict__ raw)
{
    __shared__ int ok_int, ok_float;
    int tid = threadIdx.x;
    if (tid == 0) { ok_int = 1; ok_float = 1; }
    __syncthreads();
    for (int i = tid; i < BB * LL; i += blockDim.x) {
        int v = raw[i];
        if (v != 0 && v != 1)          ok_int = 0;    // benign race: only writes 0
        if (v != 0 && v != 0x3F800000) ok_float = 0;
    }
    __syncthreads();
    const unsigned char* raw8 = (const unsigned char*)raw;
    for (int i = tid; i < BB * LL; i += blockDim.x) {
        int out;
        if (ok_int)        out = raw[i];
        else if (ok_float) out = raw[i] ? 1 : 0;
        else               out = raw8[i] ? 1 : 0;
        g_kpm[i] = out;
    }
}

// ---------------------------------------------------------------------------
// SGEMM: C[m,n] = sum_k A[m,k] * W[n,k] + bias[n]
// M=4096, N=1024, K=1024. Tile 128x64, BK=16, 256 threads, 8x4 per thread.
// ---------------------------------------------------------------------------
__global__ __launch_bounds__(256) void sgemm_bias(const float* __restrict__ A,
                                                  const float* __restrict__ W,
                                                  const float* __restrict__ bias,
                                                  float* __restrict__ C)
{
    const int K = 1024, N = 1024;
    __shared__ float As[128][17];
    __shared__ float Ws[64][17];

    int tid = threadIdx.x;
    int tx = tid & 15;         // 0..15 -> 4 cols each
    int ty = tid >> 4;         // 0..15 -> 8 rows each
    int row0 = blockIdx.y * 128;
    int col0 = blockIdx.x * 64;

    float acc[8][4];
    #pragma unroll
    for (int i = 0; i < 8; i++)
        #pragma unroll
        for (int j = 0; j < 4; j++) acc[i][j] = 0.f;

    int lr = tid >> 2;           // 0..63
    int lc = (tid & 3) * 4;      // 0,4,8,12

    for (int k0 = 0; k0 < K; k0 += 16) {
        float4 a0 = *(const float4*)(A + (size_t)(row0 + lr) * K + k0 + lc);
        float4 a1 = *(const float4*)(A + (size_t)(row0 + lr + 64) * K + k0 + lc);
        float4 w0 = *(const float4*)(W + (size_t)(col0 + lr) * K + k0 + lc);
        As[lr][lc + 0] = a0.x; As[lr][lc + 1] = a0.y; As[lr][lc + 2] = a0.z; As[lr][lc + 3] = a0.w;
        As[lr + 64][lc + 0] = a1.x; As[lr + 64][lc + 1] = a1.y; As[lr + 64][lc + 2] = a1.z; As[lr + 64][lc + 3] = a1.w;
        Ws[lr][lc + 0] = w0.x; Ws[lr][lc + 1] = w0.y; Ws[lr][lc + 2] = w0.z; Ws[lr][lc + 3] = w0.w;
        __syncthreads();

        #pragma unroll
        for (int kk = 0; kk < 16; kk++) {
            float ar[8], wr[4];
            #pragma unroll
            for (int i = 0; i < 8; i++) ar[i] = As[ty * 8 + i][kk];
            #pragma unroll
            for (int j = 0; j < 4; j++) wr[j] = Ws[tx * 4 + j][kk];
            #pragma unroll
            for (int i = 0; i < 8; i++)
                #pragma unroll
                for (int j = 0; j < 4; j++)
                    acc[i][j] += ar[i] * wr[j];
        }
        __syncthreads();
    }

    int col = col0 + tx * 4;
    float4 bv = *(const float4*)(bias + col);
    #pragma unroll
    for (int i = 0; i < 8; i++) {
        int row = row0 + ty * 8 + i;
        float4 out;
        out.x = acc[i][0] + bv.x;
        out.y = acc[i][1] + bv.y;
        out.z = acc[i][2] + bv.z;
        out.w = acc[i][3] + bv.w;
        *(float4*)(C + (size_t)row * N + col) = out;
    }
}

// ---------------------------------------------------------------------------
// Flash-style attention with role-gating bias, causal + key-padding masks.
// Grid: (L/64, H, B). Block: 256 threads. Each group of 4 threads owns one
// query row; each thread owns 16 of the 64 head-dim output columns
// (interleaved: col = g + 4*c to stay bank-conflict free on V reads).
// ---------------------------------------------------------------------------
__global__ __launch_bounds__(256) void attn_kernel(const int* __restrict__ role,
                                                   const float* __restrict__ deltap)
{
    __shared__ float Qs[64][65];
    __shared__ float Ks[32][65];
    __shared__ float Vs[32][65];
    __shared__ float Ps[64][33];
    __shared__ int   roleK[32];
    __shared__ int   kpmK[32];

    const int tid = threadIdx.x;
    const int r = tid >> 2;      // query row in tile (0..63)
    const int g = tid & 3;       // column-group / key-group id
    const int qt = blockIdx.x;
    const int h  = blockIdx.y;
    const int b  = blockIdx.z;
    const int q0 = qt * 64;
    const float delta = *deltap;
    const float scale = 0.125f;  // 1/sqrt(64)

    const size_t base = ((size_t)b * LL) * DD + (size_t)h * HDIM;

    // Load Q tile (64 x 64 floats)
    for (int i = tid; i < 64 * 16; i += 256) {
        int rr = i >> 4, cc = (i & 15) * 4;
        float4 v = *(const float4*)(g_Q + base + (size_t)(q0 + rr) * DD + cc);
        Qs[rr][cc + 0] = v.x; Qs[rr][cc + 1] = v.y; Qs[rr][cc + 2] = v.z; Qs[rr][cc + 3] = v.w;
    }

    const int qg = q0 + r;
    const int rq = role[b * LL + qg];

    float m = -INFINITY, l = 0.f;
    float O[16];
    #pragma unroll
    for (int c = 0; c < 16; c++) O[c] = 0.f;

    const int nt = qt * 2 + 2;   // causal: 32-key tiles needed to cover keys <= q0+63
    for (int t = 0; t < nt; t++) {
        const int k0 = t * 32;
        __syncthreads();   // also covers Q-tile visibility on t==0
        for (int i = tid; i < 32 * 16; i += 256) {
            int rr = i >> 4, cc = (i & 15) * 4;
            float4 kv = *(const float4*)(g_K + base + (size_t)(k0 + rr) * DD + cc);
            Ks[rr][cc + 0] = kv.x; Ks[rr][cc + 1] = kv.y; Ks[rr][cc + 2] = kv.z; Ks[rr][cc + 3] = kv.w;
            float4 vv = *(const float4*)(g_V + base + (size_t)(k0 + rr) * DD + cc);
            Vs[rr][cc + 0] = vv.x; Vs[rr][cc + 1] = vv.y; Vs[rr][cc + 2] = vv.z; Vs[rr][cc + 3] = vv.w;
        }
        if (tid < 32) {
            roleK[tid] = role[b * LL + k0 + tid];
            kpmK[tid]  = g_kpm[b * LL + k0 + tid];
        }
        __syncthreads();

        // S = Q K^T for this thread's 8 keys
        float s[8];
        #pragma unroll
        for (int i = 0; i < 8; i++) s[i] = 0.f;
        #pragma unroll 8
        for (int d = 0; d < 64; d++) {
            float qv = Qs[r][d];
            #pragma unroll
            for (int i = 0; i < 8; i++) s[i] += qv * Ks[g * 8 + i][d];
        }

        // scale + role bias + masks, tile max
        float tmax = -INFINITY;
        #pragma unroll
        for (int i = 0; i < 8; i++) {
            int kk = g * 8 + i;
            int kg = k0 + kk;
            float sv = s[i] * scale + ((rq == roleK[kk]) ? delta : 0.f);
            if (kg > qg || kpmK[kk]) sv = -INFINITY;
            s[i] = sv;
            tmax = fmaxf(tmax, sv);
        }
        tmax = fmaxf(tmax, __shfl_xor_sync(0xffffffffu, tmax, 1));
        tmax = fmaxf(tmax, __shfl_xor_sync(0xffffffffu, tmax, 2));

        float m_new = fmaxf(m, tmax);
        float alpha, psum = 0.f;
        if (m_new == -INFINITY) {
            // fully-masked so far: keep everything at zero (reference nan_to_num -> 0)
            alpha = 1.f;
            #pragma unroll
            for (int i = 0; i < 8; i++) Ps[r][g * 8 + i] = 0.f;
        } else {
            alpha = __expf(m - m_new);
            #pragma unroll
            for (int i = 0; i < 8; i++) {
                float p = __expf(s[i] - m_new);   // masked -inf -> exp -> 0
                psum += p;
                Ps[r][g * 8 + i] = p;
            }
        }
        psum += __shfl_xor_sync(0xffffffffu, psum, 1);
        psum += __shfl_xor_sync(0xffffffffu, psum, 2);
        l = l * alpha + psum;
        m = m_new;
        __syncwarp();   // Ps row written by the 4 same-warp threads of this row

        #pragma unroll
        for (int c = 0; c < 16; c++) O[c] *= alpha;
        #pragma unroll 8
        for (int kk = 0; kk < 32; kk++) {
            float p = Ps[r][kk];
            #pragma unroll
            for (int c = 0; c < 16; c++)
                O[c] += p * Vs[kk][g + 4 * c];
        }
    }

    float inv = (l > 0.f) ? (1.f / l) : 0.f;
    #pragma unroll
    for (int c = 0; c < 16; c++)
        g_A[base + (size_t)qg * DD + g + 4 * c] = O[c] * inv;
}

// ---------------------------------------------------------------------------
// Launch
// ---------------------------------------------------------------------------
extern "C" void kernel_launch(void* const* d_in, const int* in_sizes, int n_in,
                              void* d_out, int out_size)
{
    const float* x    = (const float*)d_in[0];
    const int*   role = (const int*)d_in[1];
    // d_in[2] = attn_mask (causal triu) — recomputed analytically, unused
    const int*   kpm_raw = (const int*)d_in[3];   // dtype detected on device
    const float* Wq = (const float*)d_in[4];
    const float* bq = (const float*)d_in[5];
    const float* Wk = (const float*)d_in[6];
    const float* bk = (const float*)d_in[7];
    const float* Wv = (const float*)d_in[8];
    const float* bv = (const float*)d_in[9];
    const float* Wo = (const float*)d_in[10];
    const float* bo = (const float*)d_in[11];
    const float* delta = (const float*)d_in[12];

    float *qb, *kb, *vb, *ab;
    cudaGetSymbolAddress((void**)&qb, g_Q);
    cudaGetSymbolAddress((void**)&kb, g_K);
    cudaGetSymbolAddress((void**)&vb, g_V);
    cudaGetSymbolAddress((void**)&ab, g_A);

    normalize_kpm<<<1, 256>>>(kpm_raw);

    dim3 ggrid(1024 / 64, MROWS / 128);   // (16, 32)
    sgemm_bias<<<ggrid, 256>>>(x, Wq, bq, qb);
    sgemm_bias<<<ggrid, 256>>>(x, Wk, bk, kb);
    sgemm_bias<<<ggrid, 256>>>(x, Wv, bv, vb);

    dim3 agrid(LL / 64, HH, BB);          // (32, 16, 2)
    attn_kernel<<<agrid, 256>>>(role, delta);

    sgemm_bias<<<ggrid, 256>>>(ab, Wo, bo, (float*)d_out);
}

// round 9
// speedup vs baseline: 1.0031x; 1.0031x over previous
#include <cuda_runtime.h>
#include <cuda_bf16.h>
#include <math.h>

#define BB 2
#define LL 2048
#define DD 1024
#define HH 16
#define HDIM 64
#define MROWS (BB*LL)   // 4096

// Scratch (allocation-free per harness rules): Q, K, V, attention output
static __device__ float g_Q[MROWS * DD];
static __device__ float g_K[MROWS * DD];
static __device__ float g_V[MROWS * DD];
static __device__ float g_A[MROWS * DD];
static __device__ int   g_kpm[BB * LL];   // canonical key-padding mask (0/1)

// ---------------------------------------------------------------------------
// Normalize key_padding_mask regardless of on-disk dtype.
// The reference produces jnp.bool_, but the harness only serializes
// float32/int32/bfloat16 — detect which layout we actually got.
//   int32 layout : every 32-bit word is 0 or 1
//   float32 layout: every 32-bit word is 0 or 0x3F800000 (1.0f)
//   otherwise     : treat as packed uint8
// ---------------------------------------------------------------------------
__global__ void normalize_kpm(const int* __restrict__ raw)
{
    __shared__ int ok_int, ok_float;
    int tid = threadIdx.x;
    if (tid == 0) { ok_int = 1; ok_float = 1; }
    __syncthreads();
    for (int i = tid; i < BB * LL; i += blockDim.x) {
        int v = raw[i];
        if (v != 0 && v != 1)          ok_int = 0;    // benign race: only writes 0
        if (v != 0 && v != 0x3F800000) ok_float = 0;
    }
    __syncthreads();
    const unsigned char* raw8 = (const unsigned char*)raw;
    for (int i = tid; i < BB * LL; i += blockDim.x) {
        int out;
        if (ok_int)        out = raw[i];
        else if (ok_float) out = raw[i] ? 1 : 0;
        else               out = raw8[i] ? 1 : 0;
        g_kpm[i] = out;
    }
}

// ---------------------------------------------------------------------------
// SGEMM: C[m,n] = sum_k A[m,k] * W[n,k] + bias[n]
// M=4096, N=1024, K=1024. Tile 128x64, BK=16, 256 threads, 8x4 per thread.
// ---------------------------------------------------------------------------
__global__ __launch_bounds__(256) void sgemm_bias(const float* __restrict__ A,
                                                  const float* __restrict__ W,
                                                  const float* __restrict__ bias,
                                                  float* __restrict__ C)
{
    const int K = 1024, N = 1024;
    __shared__ float As[128][17];
    __shared__ float Ws[64][17];

    int tid = threadIdx.x;
    int tx = tid & 15;         // 0..15 -> 4 cols each
    int ty = tid >> 4;         // 0..15 -> 8 rows each
    int row0 = blockIdx.y * 128;
    int col0 = blockIdx.x * 64;

    float acc[8][4];
    #pragma unroll
    for (int i = 0; i < 8; i++)
        #pragma unroll
        for (int j = 0; j < 4; j++) acc[i][j] = 0.f;

    int lr = tid >> 2;           // 0..63
    int lc = (tid & 3) * 4;      // 0,4,8,12

    for (int k0 = 0; k0 < K; k0 += 16) {
        float4 a0 = *(const float4*)(A + (size_t)(row0 + lr) * K + k0 + lc);
        float4 a1 = *(const float4*)(A + (size_t)(row0 + lr + 64) * K + k0 + lc);
        float4 w0 = *(const float4*)(W + (size_t)(col0 + lr) * K + k0 + lc);
        As[lr][lc + 0] = a0.x; As[lr][lc + 1] = a0.y; As[lr][lc + 2] = a0.z; As[lr][lc + 3] = a0.w;
        As[lr + 64][lc + 0] = a1.x; As[lr + 64][lc + 1] = a1.y; As[lr + 64][lc + 2] = a1.z; As[lr + 64][lc + 3] = a1.w;
        Ws[lr][lc + 0] = w0.x; Ws[lr][lc + 1] = w0.y; Ws[lr][lc + 2] = w0.z; Ws[lr][lc + 3] = w0.w;
        __syncthreads();

        #pragma unroll
        for (int kk = 0; kk < 16; kk++) {
            float ar[8], wr[4];
            #pragma unroll
            for (int i = 0; i < 8; i++) ar[i] = As[ty * 8 + i][kk];
            #pragma unroll
            for (int j = 0; j < 4; j++) wr[j] = Ws[tx * 4 + j][kk];
            #pragma unroll
            for (int i = 0; i < 8; i++)
                #pragma unroll
                for (int j = 0; j < 4; j++)
                    acc[i][j] += ar[i] * wr[j];
        }
        __syncthreads();
    }

    int col = col0 + tx * 4;
    float4 bv = *(const float4*)(bias + col);
    #pragma unroll
    for (int i = 0; i < 8; i++) {
        int row = row0 + ty * 8 + i;
        float4 out;
        out.x = acc[i][0] + bv.x;
        out.y = acc[i][1] + bv.y;
        out.z = acc[i][2] + bv.z;
        out.w = acc[i][3] + bv.w;
        *(float4*)(C + (size_t)row * N + col) = out;
    }
}

// ---------------------------------------------------------------------------
// Flash-style attention with role-gating bias, causal + key-padding masks.
// Grid: (L/64, H, B). Block: 256 threads. Each group of 4 threads owns one
// query row; each thread owns 16 of the 64 head-dim output columns
// (interleaved: col = g + 4*c to stay bank-conflict free on V reads).
// ---------------------------------------------------------------------------
__global__ __launch_bounds__(256) void attn_kernel(const int* __restrict__ role,
                                                   const float* __restrict__ deltap)
{
    __shared__ float Qs[64][65];
    __shared__ float Ks[32][65];
    __shared__ float Vs[32][65];
    __shared__ float Ps[64][33];
    __shared__ int   roleK[32];
    __shared__ int   kpmK[32];

    const int tid = threadIdx.x;
    const int r = tid >> 2;      // query row in tile (0..63)
    const int g = tid & 3;       // column-group / key-group id
    const int qt = blockIdx.x;
    const int h  = blockIdx.y;
    const int b  = blockIdx.z;
    const int q0 = qt * 64;
    const float delta = *deltap;
    const float scale = 0.125f;  // 1/sqrt(64)

    const size_t base = ((size_t)b * LL) * DD + (size_t)h * HDIM;

    // Load Q tile (64 x 64 floats)
    for (int i = tid; i < 64 * 16; i += 256) {
        int rr = i >> 4, cc = (i & 15) * 4;
        float4 v = *(const float4*)(g_Q + base + (size_t)(q0 + rr) * DD + cc);
        Qs[rr][cc + 0] = v.x; Qs[rr][cc + 1] = v.y; Qs[rr][cc + 2] = v.z; Qs[rr][cc + 3] = v.w;
    }

    const int qg = q0 + r;
    const int rq = role[b * LL + qg];

    float m = -INFINITY, l = 0.f;
    float O[16];
    #pragma unroll
    for (int c = 0; c < 16; c++) O[c] = 0.f;

    const int nt = qt * 2 + 2;   // causal: 32-key tiles needed to cover keys <= q0+63
    for (int t = 0; t < nt; t++) {
        const int k0 = t * 32;
        __syncthreads();   // also covers Q-tile visibility on t==0
        for (int i = tid; i < 32 * 16; i += 256) {
            int rr = i >> 4, cc = (i & 15) * 4;
            float4 kv = *(const float4*)(g_K + base + (size_t)(k0 + rr) * DD + cc);
            Ks[rr][cc + 0] = kv.x; Ks[rr][cc + 1] = kv.y; Ks[rr][cc + 2] = kv.z; Ks[rr][cc + 3] = kv.w;
            float4 vv = *(const float4*)(g_V + base + (size_t)(k0 + rr) * DD + cc);
            Vs[rr][cc + 0] = vv.x; Vs[rr][cc + 1] = vv.y; Vs[rr][cc + 2] = vv.z; Vs[rr][cc + 3] = vv.w;
        }
        if (tid < 32) {
            roleK[tid] = role[b * LL + k0 + tid];
            kpmK[tid]  = g_kpm[b * LL + k0 + tid];
        }
        __syncthreads();

        // S = Q K^T for this thread's 8 keys
        float s[8];
        #pragma unroll
        for (int i = 0; i < 8; i++) s[i] = 0.f;
        #pragma unroll 8
        for (int d = 0; d < 64; d++) {
            float qv = Qs[r][d];
            #pragma unroll
            for (int i = 0; i < 8; i++) s[i] += qv * Ks[g * 8 + i][d];
        }

        // scale + role bias + masks, tile max
        float tmax = -INFINITY;
        #pragma unroll
        for (int i = 0; i < 8; i++) {
            int kk = g * 8 + i;
            int kg = k0 + kk;
            float sv = s[i] * scale + ((rq == roleK[kk]) ? delta : 0.f);
            if (kg > qg || kpmK[kk]) sv = -INFINITY;
            s[i] = sv;
            tmax = fmaxf(tmax, sv);
        }
        tmax = fmaxf(tmax, __shfl_xor_sync(0xffffffffu, tmax, 1));
        tmax = fmaxf(tmax, __shfl_xor_sync(0xffffffffu, tmax, 2));

        float m_new = fmaxf(m, tmax);
        float alpha, psum = 0.f;
        if (m_new == -INFINITY) {
            // fully-masked so far: keep everything at zero (reference nan_to_num -> 0)
            alpha = 1.f;
            #pragma unroll
            for (int i = 0; i < 8; i++) Ps[r][g * 8 + i] = 0.f;
        } else {
            alpha = __expf(m - m_new);
            #pragma unroll
            for (int i = 0; i < 8; i++) {
                float p = __expf(s[i] - m_new);   // masked -inf -> exp -> 0
                psum += p;
                Ps[r][g * 8 + i] = p;
            }
        }
        psum += __shfl_xor_sync(0xffffffffu, psum, 1);
        psum += __shfl_xor_sync(0xffffffffu, psum, 2);
        l = l * alpha + psum;
        m = m_new;
        __syncwarp();   // Ps row written by the 4 same-warp threads of this row

        #pragma unroll
        for (int c = 0; c < 16; c++) O[c] *= alpha;
        #pragma unroll 8
        for (int kk = 0; kk < 32; kk++) {
            float p = Ps[r][kk];
            #pragma unroll
            for (int c = 0; c < 16; c++)
                O[c] += p * Vs[kk][g + 4 * c];
        }
    }

    float inv = (l > 0.f) ? (1.f / l) : 0.f;
    #pragma unroll
    for (int c = 0; c < 16; c++)
        g_A[base + (size_t)qg * DD + g + 4 * c] = O[c] * inv;
}

// ---------------------------------------------------------------------------
// Launch
// ---------------------------------------------------------------------------
extern "C" void kernel_launch(void* const* d_in, const int* in_sizes, int n_in,
                              void* d_out, int out_size)
{
    const float* x    = (const float*)d_in[0];
    const int*   role = (const int*)d_in[1];
    // d_in[2] = attn_mask (causal triu) — recomputed analytically, unused
    const int*   kpm_raw = (const int*)d_in[3];   // dtype detected on device
    const float* Wq = (const float*)d_in[4];
    const float* bq = (const float*)d_in[5];
    const float* Wk = (const float*)d_in[6];
    const float* bk = (const float*)d_in[7];
    const float* Wv = (const float*)d_in[8];
    const float* bv = (const float*)d_in[9];
    const float* Wo = (const float*)d_in[10];
    const float* bo = (const float*)d_in[11];
    const float* delta = (const float*)d_in[12];

    float *qb, *kb, *vb, *ab;
    cudaGetSymbolAddress((void**)&qb, g_Q);
    cudaGetSymbolAddress((void**)&kb, g_K);
    cudaGetSymbolAddress((void**)&vb, g_V);
    cudaGetSymbolAddress((void**)&ab, g_A);

    normalize_kpm<<<1, 256>>>(kpm_raw);

    dim3 ggrid(1024 / 64, MROWS / 128);   // (16, 32)
    sgemm_bias<<<ggrid, 256>>>(x, Wq, bq, qb);
    sgemm_bias<<<ggrid, 256>>>(x, Wk, bk, kb);
    sgemm_bias<<<ggrid, 256>>>(x, Wv, bv, vb);

    dim3 agrid(LL / 64, HH, BB);          // (32, 16, 2)
    attn_kernel<<<agrid, 256>>>(role, delta);

    sgemm_bias<<<ggrid, 256>>>(ab, Wo, bo, (float*)d_out);
}

// round 10
// speedup vs baseline: 1.4825x; 1.4780x over previous
#include <cuda_runtime.h>
#include <cuda_bf16.h>
#include <math.h>
#include <stdint.h>

#define BB 2
#define LL 2048
#define DD 1024
#define HH 16
#define HDIM 64
#define MROWS (BB*LL)   // 4096

// Scratch (allocation-free per harness rules)
static __device__ float g_Q[MROWS * DD];
static __device__ float g_K[MROWS * DD];
static __device__ float g_V[MROWS * DD];
static __device__ float g_A[MROWS * DD];
static __device__ int   g_kpm[BB * LL];

// ---------------------------------------------------------------------------
// Normalize key_padding_mask regardless of on-disk dtype (worked in R9).
// ---------------------------------------------------------------------------
__global__ void normalize_kpm(const int* __restrict__ raw)
{
    __shared__ int ok_int, ok_float;
    int tid = threadIdx.x;
    if (tid == 0) { ok_int = 1; ok_float = 1; }
    __syncthreads();
    for (int i = tid; i < BB * LL; i += blockDim.x) {
        int v = raw[i];
        if (v != 0 && v != 1)          ok_int = 0;
        if (v != 0 && v != 0x3F800000) ok_float = 0;
    }
    __syncthreads();
    const unsigned char* raw8 = (const unsigned char*)raw;
    for (int i = tid; i < BB * LL; i += blockDim.x) {
        int out;
        if (ok_int)        out = raw[i];
        else if (ok_float) out = raw[i] ? 1 : 0;
        else               out = raw8[i] ? 1 : 0;
        g_kpm[i] = out;
    }
}

// ---------------------------------------------------------------------------
// tf32 helpers
// ---------------------------------------------------------------------------
__device__ __forceinline__ void tf32split(float x, float& hi, float& lo)
{
    uint32_t h;
    asm("cvt.rna.tf32.f32 %0, %1;" : "=r"(h) : "f"(x));
    hi = __uint_as_float(h);
    float r = x - hi;
    uint32_t l;
    asm("cvt.rna.tf32.f32 %0, %1;" : "=r"(l) : "f"(r));
    lo = __uint_as_float(l);
}

__device__ __forceinline__ void mma_tf32(float* c, const uint32_t* a,
                                         uint32_t b0, uint32_t b1)
{
    asm volatile(
        "mma.sync.aligned.m16n8k8.row.col.f32.tf32.tf32.f32 "
        "{%0,%1,%2,%3}, {%4,%5,%6,%7}, {%8,%9}, {%0,%1,%2,%3};\n"
        : "+f"(c[0]), "+f"(c[1]), "+f"(c[2]), "+f"(c[3])
        : "r"(a[0]), "r"(a[1]), "r"(a[2]), "r"(a[3]), "r"(b0), "r"(b1));
}

// ---------------------------------------------------------------------------
// GEMM (tensor core, tf32x3): C[m,n] = sum_k A[m,k]*W[n,k] + bias[n]
// M=4096, N=1024, K=1024. Block tile 128x128, BK=16, 256 threads (8 warps).
// Warp tile 32x64 = 2 m16 x 8 n8 mma tiles. 3 passes: hi*hi, lo*hi, hi*lo.
// ---------------------------------------------------------------------------
#define GSTRIDE 20   // smem row stride in floats (conflict-free: (20r+k)%32 distinct)

__global__ __launch_bounds__(256) void gemm_tf32x3(const float* __restrict__ A,
                                                   const float* __restrict__ W,
                                                   const float* __restrict__ bias,
                                                   float* __restrict__ C)
{
    const int K = 1024, N = 1024;
    __shared__ float Ah[128 * GSTRIDE];
    __shared__ float Al[128 * GSTRIDE];
    __shared__ float Wh[128 * GSTRIDE];
    __shared__ float Wl[128 * GSTRIDE];

    const int tid  = threadIdx.x;
    const int lane = tid & 31;
    const int wid  = tid >> 5;
    const int wm   = wid & 3;      // 0..3 -> 32-row slice
    const int wn   = wid >> 2;     // 0..1 -> 64-col slice
    const int row0 = blockIdx.y * 128;
    const int col0 = blockIdx.x * 128;

    const int lrow = tid >> 1;        // 0..127 (load row)
    const int lf   = (tid & 1) * 8;   // k offset 0 or 8

    float c[2][8][4];
    #pragma unroll
    for (int mt = 0; mt < 2; mt++)
        #pragma unroll
        for (int nt = 0; nt < 8; nt++)
            #pragma unroll
            for (int e = 0; e < 4; e++) c[mt][nt][e] = 0.f;

    const int g4 = lane >> 2;   // groupID
    const int t4 = lane & 3;    // threadIDInGroup

    for (int k0 = 0; k0 < K; k0 += 16) {
        // global loads (2 float4 each for A and W rows)
        float4 a0 = *(const float4*)(A + (size_t)(row0 + lrow) * K + k0 + lf);
        float4 a1 = *(const float4*)(A + (size_t)(row0 + lrow) * K + k0 + lf + 4);
        float4 w0 = *(const float4*)(W + (size_t)(col0 + lrow) * K + k0 + lf);
        float4 w1 = *(const float4*)(W + (size_t)(col0 + lrow) * K + k0 + lf + 4);

        __syncthreads();   // previous compute done before overwriting smem

        {
            float4 h, l;
            tf32split(a0.x, h.x, l.x); tf32split(a0.y, h.y, l.y);
            tf32split(a0.z, h.z, l.z); tf32split(a0.w, h.w, l.w);
            *(float4*)&Ah[lrow * GSTRIDE + lf] = h;
            *(float4*)&Al[lrow * GSTRIDE + lf] = l;
            tf32split(a1.x, h.x, l.x); tf32split(a1.y, h.y, l.y);
            tf32split(a1.z, h.z, l.z); tf32split(a1.w, h.w, l.w);
            *(float4*)&Ah[lrow * GSTRIDE + lf + 4] = h;
            *(float4*)&Al[lrow * GSTRIDE + lf + 4] = l;
            tf32split(w0.x, h.x, l.x); tf32split(w0.y, h.y, l.y);
            tf32split(w0.z, h.z, l.z); tf32split(w0.w, h.w, l.w);
            *(float4*)&Wh[lrow * GSTRIDE + lf] = h;
            *(float4*)&Wl[lrow * GSTRIDE + lf] = l;
            tf32split(w1.x, h.x, l.x); tf32split(w1.y, h.y, l.y);
            tf32split(w1.z, h.z, l.z); tf32split(w1.w, h.w, l.w);
            *(float4*)&Wh[lrow * GSTRIDE + lf + 4] = h;
            *(float4*)&Wl[lrow * GSTRIDE + lf + 4] = l;
        }
        __syncthreads();

        #pragma unroll
        for (int kk = 0; kk < 2; kk++) {
            const int ko = kk * 8;
            uint32_t ah[2][4], al[2][4];
            #pragma unroll
            for (int mt = 0; mt < 2; mt++) {
                int r = wm * 32 + mt * 16 + g4;
                int kc = ko + t4;
                ah[mt][0] = __float_as_uint(Ah[r * GSTRIDE + kc]);
                ah[mt][1] = __float_as_uint(Ah[(r + 8) * GSTRIDE + kc]);
                ah[mt][2] = __float_as_uint(Ah[r * GSTRIDE + kc + 4]);
                ah[mt][3] = __float_as_uint(Ah[(r + 8) * GSTRIDE + kc + 4]);
                al[mt][0] = __float_as_uint(Al[r * GSTRIDE + kc]);
                al[mt][1] = __float_as_uint(Al[(r + 8) * GSTRIDE + kc]);
                al[mt][2] = __float_as_uint(Al[r * GSTRIDE + kc + 4]);
                al[mt][3] = __float_as_uint(Al[(r + 8) * GSTRIDE + kc + 4]);
            }
            #pragma unroll
            for (int nt = 0; nt < 8; nt++) {
                int cc = wn * 64 + nt * 8 + g4;
                int kc = ko + t4;
                uint32_t bh0 = __float_as_uint(Wh[cc * GSTRIDE + kc]);
                uint32_t bh1 = __float_as_uint(Wh[cc * GSTRIDE + kc + 4]);
                uint32_t bl0 = __float_as_uint(Wl[cc * GSTRIDE + kc]);
                uint32_t bl1 = __float_as_uint(Wl[cc * GSTRIDE + kc + 4]);
                #pragma unroll
                for (int mt = 0; mt < 2; mt++) {
                    mma_tf32(c[mt][nt], ah[mt], bh0, bh1);   // hi*hi
                    mma_tf32(c[mt][nt], al[mt], bh0, bh1);   // lo*hi
                    mma_tf32(c[mt][nt], ah[mt], bl0, bl1);   // hi*lo
                }
            }
        }
    }

    // Epilogue
    #pragma unroll
    for (int mt = 0; mt < 2; mt++) {
        #pragma unroll
        for (int nt = 0; nt < 8; nt++) {
            int r  = row0 + wm * 32 + mt * 16 + g4;
            int cc = col0 + wn * 64 + nt * 8 + t4 * 2;
            float b0v = bias[cc], b1v = bias[cc + 1];
            C[(size_t)r * N + cc]           = c[mt][nt][0] + b0v;
            C[(size_t)r * N + cc + 1]       = c[mt][nt][1] + b1v;
            C[(size_t)(r + 8) * N + cc]     = c[mt][nt][2] + b0v;
            C[(size_t)(r + 8) * N + cc + 1] = c[mt][nt][3] + b1v;
        }
    }
}

// ---------------------------------------------------------------------------
// Flash attention, fp32, 64q x 64k tiles, 4x4 register blocking.
// Block 256 threads: tyq = tid>>4 (row group of 4 queries), txk = tid&15.
// Row-group = 16 threads sharing tyq = one contiguous half-warp -> shfl reduce.
// Dynamic smem: Qs,Ks,Vs,Ps [64][68] + roleK[64] + kpmK[64]  (~70 KB).
// ---------------------------------------------------------------------------
#define ASTRIDE 68
#define ATN_SMEM (4 * 64 * ASTRIDE * 4 + 2 * 64 * 4)

__global__ __launch_bounds__(256) void attn_kernel(const int* __restrict__ role,
                                                   const float* __restrict__ deltap)
{
    extern __shared__ float sm[];
    float* Qs = sm;
    float* Ks = Qs + 64 * ASTRIDE;
    float* Vs = Ks + 64 * ASTRIDE;
    float* Ps = Vs + 64 * ASTRIDE;
    int*   roleK = (int*)(Ps + 64 * ASTRIDE);
    int*   kpmK  = roleK + 64;

    const int tid = threadIdx.x;
    const int tyq = tid >> 4;     // 0..15
    const int txk = tid & 15;     // 0..15
    const int qt = blockIdx.x;
    const int h  = blockIdx.y;
    const int b  = blockIdx.z;
    const int q0 = qt * 64;
    const float delta = *deltap;
    const float scale = 0.125f;

    const size_t base = ((size_t)b * LL) * DD + (size_t)h * HDIM;

    // Load Q tile: 64 rows x 16 float4
    for (int i = tid; i < 64 * 16; i += 256) {
        int rr = i >> 4, cc = (i & 15) * 4;
        float4 v = *(const float4*)(g_Q + base + (size_t)(q0 + rr) * DD + cc);
        *(float4*)&Qs[rr * ASTRIDE + cc] = v;
    }

    int rq[4];
    #pragma unroll
    for (int i = 0; i < 4; i++) rq[i] = role[b * LL + q0 + 4 * tyq + i];

    float m[4], l[4], O[4][4];
    #pragma unroll
    for (int i = 0; i < 4; i++) {
        m[i] = -INFINITY; l[i] = 0.f;
        #pragma unroll
        for (int j = 0; j < 4; j++) O[i][j] = 0.f;
    }

    for (int t = 0; t <= qt; t++) {
        const int k0t = t * 64;
        __syncthreads();   // smem reuse from previous iter (and Q on t==0)

        for (int i = tid; i < 64 * 16; i += 256) {
            int rr = i >> 4, cc = (i & 15) * 4;
            *(float4*)&Ks[rr * ASTRIDE + cc] =
                *(const float4*)(g_K + base + (size_t)(k0t + rr) * DD + cc);
            *(float4*)&Vs[rr * ASTRIDE + cc] =
                *(const float4*)(g_V + base + (size_t)(k0t + rr) * DD + cc);
        }
        if (tid < 64) {
            roleK[tid] = role[b * LL + k0t + tid];
            kpmK[tid]  = g_kpm[b * LL + k0t + tid];
        }
        __syncthreads();

        // S = Q K^T  (4x4 per thread)
        float s[4][4];
        #pragma unroll
        for (int i = 0; i < 4; i++)
            #pragma unroll
            for (int j = 0; j < 4; j++) s[i][j] = 0.f;

        #pragma unroll 4
        for (int k0 = 0; k0 < 64; k0 += 4) {
            float4 qv[4], kv[4];
            #pragma unroll
            for (int i = 0; i < 4; i++) qv[i] = *(const float4*)&Qs[(4 * tyq + i) * ASTRIDE + k0];
            #pragma unroll
            for (int j = 0; j < 4; j++) kv[j] = *(const float4*)&Ks[(4 * txk + j) * ASTRIDE + k0];
            #pragma unroll
            for (int i = 0; i < 4; i++)
                #pragma unroll
                for (int j = 0; j < 4; j++)
                    s[i][j] += qv[i].x * kv[j].x + qv[i].y * kv[j].y
                             + qv[i].z * kv[j].z + qv[i].w * kv[j].w;
        }

        // softmax (online) per row
        float alpha_r[4];
        #pragma unroll
        for (int i = 0; i < 4; i++) {
            const int qgl = q0 + 4 * tyq + i;
            float sv[4];
            float tmax = -INFINITY;
            #pragma unroll
            for (int j = 0; j < 4; j++) {
                int kk = 4 * txk + j;
                float v = s[i][j] * scale + ((rq[i] == roleK[kk]) ? delta : 0.f);
                if ((k0t + kk) > qgl || kpmK[kk]) v = -INFINITY;
                sv[j] = v;
                tmax = fmaxf(tmax, v);
            }
            tmax = fmaxf(tmax, __shfl_xor_sync(0xffffffffu, tmax, 1));
            tmax = fmaxf(tmax, __shfl_xor_sync(0xffffffffu, tmax, 2));
            tmax = fmaxf(tmax, __shfl_xor_sync(0xffffffffu, tmax, 4));
            tmax = fmaxf(tmax, __shfl_xor_sync(0xffffffffu, tmax, 8));

            float mn = fmaxf(m[i], tmax);
            float alpha, ps = 0.f;
            float4 p4;
            if (mn == -INFINITY) {
                alpha = 1.f;
                p4.x = p4.y = p4.z = p4.w = 0.f;
            } else {
                alpha = __expf(m[i] - mn);
                p4.x = __expf(sv[0] - mn);
                p4.y = __expf(sv[1] - mn);
                p4.z = __expf(sv[2] - mn);
                p4.w = __expf(sv[3] - mn);
                ps = p4.x + p4.y + p4.z + p4.w;
            }
            *(float4*)&Ps[(4 * tyq + i) * ASTRIDE + 4 * txk] = p4;
            ps += __shfl_xor_sync(0xffffffffu, ps, 1);
            ps += __shfl_xor_sync(0xffffffffu, ps, 2);
            ps += __shfl_xor_sync(0xffffffffu, ps, 4);
            ps += __shfl_xor_sync(0xffffffffu, ps, 8);
            l[i] = l[i] * alpha + ps;
            m[i] = mn;
            alpha_r[i] = alpha;
        }
        __syncwarp();   // Ps rows written/read within the same half-warp group

        #pragma unroll
        for (int i = 0; i < 4; i++)
            #pragma unroll
            for (int j = 0; j < 4; j++) O[i][j] *= alpha_r[i];

        // O += P V   (4x4 per thread over 64 keys)
        #pragma unroll 4
        for (int kk0 = 0; kk0 < 64; kk0 += 4) {
            float4 pv[4], vv[4];
            #pragma unroll
            for (int i = 0; i < 4; i++) pv[i] = *(const float4*)&Ps[(4 * tyq + i) * ASTRIDE + kk0];
            #pragma unroll
            for (int k = 0; k < 4; k++) vv[k] = *(const float4*)&Vs[(kk0 + k) * ASTRIDE + 4 * txk];
            #pragma unroll
            for (int i = 0; i < 4; i++) {
                O[i][0] += pv[i].x * vv[0].x + pv[i].y * vv[1].x + pv[i].z * vv[2].x + pv[i].w * vv[3].x;
                O[i][1] += pv[i].x * vv[0].y + pv[i].y * vv[1].y + pv[i].z * vv[2].y + pv[i].w * vv[3].y;
                O[i][2] += pv[i].x * vv[0].z + pv[i].y * vv[1].z + pv[i].z * vv[2].z + pv[i].w * vv[3].z;
                O[i][3] += pv[i].x * vv[0].w + pv[i].y * vv[1].w + pv[i].z * vv[2].w + pv[i].w * vv[3].w;
            }
        }
    }

    #pragma unroll
    for (int i = 0; i < 4; i++) {
        float inv = (l[i] > 0.f) ? (1.f / l[i]) : 0.f;
        float4 o;
        o.x = O[i][0] * inv; o.y = O[i][1] * inv;
        o.z = O[i][2] * inv; o.w = O[i][3] * inv;
        *(float4*)(g_A + base + (size_t)(q0 + 4 * tyq + i) * DD + 4 * txk) = o;
    }
}

// ---------------------------------------------------------------------------
// Launch
// ---------------------------------------------------------------------------
extern "C" void kernel_launch(void* const* d_in, const int* in_sizes, int n_in,
                              void* d_out, int out_size)
{
    const float* x    = (const float*)d_in[0];
    const int*   role = (const int*)d_in[1];
    const int*   kpm_raw = (const int*)d_in[3];
    const float* Wq = (const float*)d_in[4];
    const float* bq = (const float*)d_in[5];
    const float* Wk = (const float*)d_in[6];
    const float* bk = (const float*)d_in[7];
    const float* Wv = (const float*)d_in[8];
    const float* bv = (const float*)d_in[9];
    const float* Wo = (const float*)d_in[10];
    const float* bo = (const float*)d_in[11];
    const float* delta = (const float*)d_in[12];

    float *qb, *kb, *vb, *ab;
    cudaGetSymbolAddress((void**)&qb, g_Q);
    cudaGetSymbolAddress((void**)&kb, g_K);
    cudaGetSymbolAddress((void**)&vb, g_V);
    cudaGetSymbolAddress((void**)&ab, g_A);

    cudaFuncSetAttribute(attn_kernel,
                         cudaFuncAttributeMaxDynamicSharedMemorySize, ATN_SMEM);

    normalize_kpm<<<1, 256>>>(kpm_raw);

    dim3 ggrid(1024 / 128, MROWS / 128);   // (8, 32)
    gemm_tf32x3<<<ggrid, 256>>>(x, Wq, bq, qb);
    gemm_tf32x3<<<ggrid, 256>>>(x, Wk, bk, kb);
    gemm_tf32x3<<<ggrid, 256>>>(x, Wv, bv, vb);

    dim3 agrid(LL / 64, HH, BB);           // (32, 16, 2)
    attn_kernel<<<agrid, 256, ATN_SMEM>>>(role, delta);

    gemm_tf32x3<<<ggrid, 256>>>(ab, Wo, bo, (float*)d_out);
}

// round 11
// speedup vs baseline: 2.0158x; 1.3598x over previous
#include <cuda_runtime.h>
#include <cuda_bf16.h>
#include <math.h>
#include <stdint.h>

#define BB 2
#define LL 2048
#define DD 1024
#define HH 16
#define HDIM 64
#define MROWS (BB*LL)   // 4096

// Scratch (allocation-free per harness rules)
static __device__ float g_Q[MROWS * DD];
static __device__ float g_K[MROWS * DD];
static __device__ float g_V[MROWS * DD];
static __device__ float g_A[MROWS * DD];
static __device__ int   g_kpm[BB * LL];

// ---------------------------------------------------------------------------
// Normalize key_padding_mask regardless of on-disk dtype (validated R9/R10).
// ---------------------------------------------------------------------------
__global__ void normalize_kpm(const int* __restrict__ raw)
{
    __shared__ int ok_int, ok_float;
    int tid = threadIdx.x;
    if (tid == 0) { ok_int = 1; ok_float = 1; }
    __syncthreads();
    for (int i = tid; i < BB * LL; i += blockDim.x) {
        int v = raw[i];
        if (v != 0 && v != 1)          ok_int = 0;
        if (v != 0 && v != 0x3F800000) ok_float = 0;
    }
    __syncthreads();
    const unsigned char* raw8 = (const unsigned char*)raw;
    for (int i = tid; i < BB * LL; i += blockDim.x) {
        int out;
        if (ok_int)        out = raw[i];
        else if (ok_float) out = raw[i] ? 1 : 0;
        else               out = raw8[i] ? 1 : 0;
        g_kpm[i] = out;
    }
}

// ---------------------------------------------------------------------------
// tf32 helpers
// ---------------------------------------------------------------------------
__device__ __forceinline__ void tf32split(float x, float& hi, float& lo)
{
    uint32_t h;
    asm("cvt.rna.tf32.f32 %0, %1;" : "=r"(h) : "f"(x));
    hi = __uint_as_float(h);
    float r = x - hi;
    uint32_t l;
    asm("cvt.rna.tf32.f32 %0, %1;" : "=r"(l) : "f"(r));
    lo = __uint_as_float(l);
}

__device__ __forceinline__ void mma_tf32(float* c, const uint32_t* a,
                                         uint32_t b0, uint32_t b1)
{
    asm volatile(
        "mma.sync.aligned.m16n8k8.row.col.f32.tf32.tf32.f32 "
        "{%0,%1,%2,%3}, {%4,%5,%6,%7}, {%8,%9}, {%0,%1,%2,%3};\n"
        : "+f"(c[0]), "+f"(c[1]), "+f"(c[2]), "+f"(c[3])
        : "r"(a[0]), "r"(a[1]), "r"(a[2]), "r"(a[3]), "r"(b0), "r"(b1));
}

// ---------------------------------------------------------------------------
// GEMM (tensor core, tf32x3): C[m,n] = sum_k A[m,k]*W[n,k] + bias[n]
// Unchanged from R10 (passing, 183 us).
// ---------------------------------------------------------------------------
#define GSTRIDE 20

__global__ __launch_bounds__(256) void gemm_tf32x3(const float* __restrict__ A,
                                                   const float* __restrict__ W,
                                                   const float* __restrict__ bias,
                                                   float* __restrict__ C)
{
    const int K = 1024, N = 1024;
    __shared__ float Ah[128 * GSTRIDE];
    __shared__ float Al[128 * GSTRIDE];
    __shared__ float Wh[128 * GSTRIDE];
    __shared__ float Wl[128 * GSTRIDE];

    const int tid  = threadIdx.x;
    const int lane = tid & 31;
    const int wid  = tid >> 5;
    const int wm   = wid & 3;
    const int wn   = wid >> 2;
    const int row0 = blockIdx.y * 128;
    const int col0 = blockIdx.x * 128;

    const int lrow = tid >> 1;
    const int lf   = (tid & 1) * 8;

    float c[2][8][4];
    #pragma unroll
    for (int mt = 0; mt < 2; mt++)
        #pragma unroll
        for (int nt = 0; nt < 8; nt++)
            #pragma unroll
            for (int e = 0; e < 4; e++) c[mt][nt][e] = 0.f;

    const int g4 = lane >> 2;
    const int t4 = lane & 3;

    for (int k0 = 0; k0 < K; k0 += 16) {
        float4 a0 = *(const float4*)(A + (size_t)(row0 + lrow) * K + k0 + lf);
        float4 a1 = *(const float4*)(A + (size_t)(row0 + lrow) * K + k0 + lf + 4);
        float4 w0 = *(const float4*)(W + (size_t)(col0 + lrow) * K + k0 + lf);
        float4 w1 = *(const float4*)(W + (size_t)(col0 + lrow) * K + k0 + lf + 4);

        __syncthreads();

        {
            float4 h, l;
            tf32split(a0.x, h.x, l.x); tf32split(a0.y, h.y, l.y);
            tf32split(a0.z, h.z, l.z); tf32split(a0.w, h.w, l.w);
            *(float4*)&Ah[lrow * GSTRIDE + lf] = h;
            *(float4*)&Al[lrow * GSTRIDE + lf] = l;
            tf32split(a1.x, h.x, l.x); tf32split(a1.y, h.y, l.y);
            tf32split(a1.z, h.z, l.z); tf32split(a1.w, h.w, l.w);
            *(float4*)&Ah[lrow * GSTRIDE + lf + 4] = h;
            *(float4*)&Al[lrow * GSTRIDE + lf + 4] = l;
            tf32split(w0.x, h.x, l.x); tf32split(w0.y, h.y, l.y);
            tf32split(w0.z, h.z, l.z); tf32split(w0.w, h.w, l.w);
            *(float4*)&Wh[lrow * GSTRIDE + lf] = h;
            *(float4*)&Wl[lrow * GSTRIDE + lf] = l;
            tf32split(w1.x, h.x, l.x); tf32split(w1.y, h.y, l.y);
            tf32split(w1.z, h.z, l.z); tf32split(w1.w, h.w, l.w);
            *(float4*)&Wh[lrow * GSTRIDE + lf + 4] = h;
            *(float4*)&Wl[lrow * GSTRIDE + lf + 4] = l;
        }
        __syncthreads();

        #pragma unroll
        for (int kk = 0; kk < 2; kk++) {
            const int ko = kk * 8;
            uint32_t ah[2][4], al[2][4];
            #pragma unroll
            for (int mt = 0; mt < 2; mt++) {
                int r = wm * 32 + mt * 16 + g4;
                int kc = ko + t4;
                ah[mt][0] = __float_as_uint(Ah[r * GSTRIDE + kc]);
                ah[mt][1] = __float_as_uint(Ah[(r + 8) * GSTRIDE + kc]);
                ah[mt][2] = __float_as_uint(Ah[r * GSTRIDE + kc + 4]);
                ah[mt][3] = __float_as_uint(Ah[(r + 8) * GSTRIDE + kc + 4]);
                al[mt][0] = __float_as_uint(Al[r * GSTRIDE + kc]);
                al[mt][1] = __float_as_uint(Al[(r + 8) * GSTRIDE + kc]);
                al[mt][2] = __float_as_uint(Al[r * GSTRIDE + kc + 4]);
                al[mt][3] = __float_as_uint(Al[(r + 8) * GSTRIDE + kc + 4]);
            }
            #pragma unroll
            for (int nt = 0; nt < 8; nt++) {
                int cc = wn * 64 + nt * 8 + g4;
                int kc = ko + t4;
                uint32_t bh0 = __float_as_uint(Wh[cc * GSTRIDE + kc]);
                uint32_t bh1 = __float_as_uint(Wh[cc * GSTRIDE + kc + 4]);
                uint32_t bl0 = __float_as_uint(Wl[cc * GSTRIDE + kc]);
                uint32_t bl1 = __float_as_uint(Wl[cc * GSTRIDE + kc + 4]);
                #pragma unroll
                for (int mt = 0; mt < 2; mt++) {
                    mma_tf32(c[mt][nt], ah[mt], bh0, bh1);
                    mma_tf32(c[mt][nt], al[mt], bh0, bh1);
                    mma_tf32(c[mt][nt], ah[mt], bl0, bl1);
                }
            }
        }
    }

    #pragma unroll
    for (int mt = 0; mt < 2; mt++) {
        #pragma unroll
        for (int nt = 0; nt < 8; nt++) {
            int r  = row0 + wm * 32 + mt * 16 + g4;
            int cc = col0 + wn * 64 + nt * 8 + t4 * 2;
            float b0v = bias[cc], b1v = bias[cc + 1];
            C[(size_t)r * N + cc]           = c[mt][nt][0] + b0v;
            C[(size_t)r * N + cc + 1]       = c[mt][nt][1] + b1v;
            C[(size_t)(r + 8) * N + cc]     = c[mt][nt][2] + b0v;
            C[(size_t)(r + 8) * N + cc + 1] = c[mt][nt][3] + b1v;
        }
    }
}

// ---------------------------------------------------------------------------
// Tensor-core flash attention (tf32x3 for S=QK^T and O=PV).
// Block: 256 threads = 8 warps; warp w owns q rows [16w,16w+16) of a 128-row
// q tile. Key tiles of 64. Grid (L/128, H, B) = (16,16,2).
// Fragment layouts verified by the passing gemm_tf32x3:
//   A: a0=A[g4][t4]   a1=A[g4+8][t4]   a2=A[g4][t4+4]   a3=A[g4+8][t4+4]
//   B: b0=Bmat[n=g4][k=t4]  b1=Bmat[g4][t4+4]   (Bmat stored [N][K])
//   C: c0=(g4,2t4) c1=(g4,2t4+1) c2=(g4+8,2t4) c3=(g4+8,2t4+1)
// P is re-laid out from C-layout to A-layout via intra-quad shuffles.
// smem strides chosen bank-conflict-free: Q/K stride 68 (4g4+t4 distinct),
// V stride 72 (8t4+g4 distinct).
// ---------------------------------------------------------------------------
#define QSTR 68
#define KSTR 68
#define VSTR 72
#define ATT_SMEM ((2*128*QSTR + 2*64*KSTR + 2*64*VSTR + 128) * 4)

__global__ __launch_bounds__(256, 1) void attn_mma(const int* __restrict__ role,
                                                   const float* __restrict__ deltap)
{
    extern __shared__ float sm[];
    float* Qh = sm;
    float* Ql = Qh + 128 * QSTR;
    float* Kh = Ql + 128 * QSTR;
    float* Kl = Kh + 64 * KSTR;
    float* Vh = Kl + 64 * KSTR;
    float* Vl = Vh + 64 * VSTR;
    int* roleK = (int*)(Vl + 64 * VSTR);
    int* kpmK  = roleK + 64;

    const int tid  = threadIdx.x;
    const int lane = tid & 31;
    const int w    = tid >> 5;
    const int g4   = lane >> 2;
    const int t4   = lane & 3;
    const int qt = blockIdx.x, h = blockIdx.y, b = blockIdx.z;
    const int q0 = qt * 128;
    const float delta = *deltap;
    const float scale = 0.125f;
    const size_t base = ((size_t)b * LL) * DD + (size_t)h * HDIM;
    const unsigned FULL = 0xffffffffu;

    // Load + split Q tile (128 x 64)
    for (int i = tid; i < 128 * 16; i += 256) {
        int rr = i >> 4, cc = (i & 15) * 4;
        float4 v = *(const float4*)(g_Q + base + (size_t)(q0 + rr) * DD + cc);
        float4 hh, ll;
        tf32split(v.x, hh.x, ll.x); tf32split(v.y, hh.y, ll.y);
        tf32split(v.z, hh.z, ll.z); tf32split(v.w, hh.w, ll.w);
        *(float4*)&Qh[rr * QSTR + cc] = hh;
        *(float4*)&Ql[rr * QSTR + cc] = ll;
    }

    const int r0  = 16 * w + g4;       // warp-local q row (and r0+8)
    const int qg0 = q0 + r0;
    const int qg1 = qg0 + 8;
    const int rq0 = role[b * LL + qg0];
    const int rq1 = role[b * LL + qg1];

    float m0 = -INFINITY, m1 = -INFINITY, l0 = 0.f, l1 = 0.f;
    float O[8][4];
    #pragma unroll
    for (int n = 0; n < 8; n++)
        #pragma unroll
        for (int e = 0; e < 4; e++) O[n][e] = 0.f;

    const int ntiles = 2 * qt + 2;
    for (int t = 0; t < ntiles; t++) {
        const int k0t = t * 64;
        __syncthreads();   // previous iter reads done; also Q visibility at t==0

        for (int i = tid; i < 64 * 16; i += 256) {
            int rr = i >> 4, cc = (i & 15) * 4;
            float4 kv = *(const float4*)(g_K + base + (size_t)(k0t + rr) * DD + cc);
            float4 hh, ll;
            tf32split(kv.x, hh.x, ll.x); tf32split(kv.y, hh.y, ll.y);
            tf32split(kv.z, hh.z, ll.z); tf32split(kv.w, hh.w, ll.w);
            *(float4*)&Kh[rr * KSTR + cc] = hh;
            *(float4*)&Kl[rr * KSTR + cc] = ll;
            float4 vv = *(const float4*)(g_V + base + (size_t)(k0t + rr) * DD + cc);
            tf32split(vv.x, hh.x, ll.x); tf32split(vv.y, hh.y, ll.y);
            tf32split(vv.z, hh.z, ll.z); tf32split(vv.w, hh.w, ll.w);
            *(float4*)&Vh[rr * VSTR + cc] = hh;
            *(float4*)&Vl[rr * VSTR + cc] = ll;
        }
        if (tid < 64) {
            roleK[tid] = role[b * LL + k0t + tid];
            kpmK[tid]  = g_kpm[b * LL + k0t + tid];
        }
        __syncthreads();

        // ---- S = Q K^T : 8 n-tiles (keys) x 8 k-steps (hd), x3 passes ----
        float sc[8][4];
        #pragma unroll
        for (int j = 0; j < 8; j++)
            #pragma unroll
            for (int e = 0; e < 4; e++) sc[j][e] = 0.f;

        #pragma unroll
        for (int ks = 0; ks < 8; ks++) {
            const int kc = ks * 8 + t4;
            uint32_t ah[4], al[4];
            ah[0] = __float_as_uint(Qh[r0 * QSTR + kc]);
            ah[1] = __float_as_uint(Qh[(r0 + 8) * QSTR + kc]);
            ah[2] = __float_as_uint(Qh[r0 * QSTR + kc + 4]);
            ah[3] = __float_as_uint(Qh[(r0 + 8) * QSTR + kc + 4]);
            al[0] = __float_as_uint(Ql[r0 * QSTR + kc]);
            al[1] = __float_as_uint(Ql[(r0 + 8) * QSTR + kc]);
            al[2] = __float_as_uint(Ql[r0 * QSTR + kc + 4]);
            al[3] = __float_as_uint(Ql[(r0 + 8) * QSTR + kc + 4]);
            #pragma unroll
            for (int j = 0; j < 8; j++) {
                const int kr = 8 * j + g4;
                uint32_t bh0 = __float_as_uint(Kh[kr * KSTR + kc]);
                uint32_t bh1 = __float_as_uint(Kh[kr * KSTR + kc + 4]);
                uint32_t bl0 = __float_as_uint(Kl[kr * KSTR + kc]);
                uint32_t bl1 = __float_as_uint(Kl[kr * KSTR + kc + 4]);
                mma_tf32(sc[j], ah, bh0, bh1);
                mma_tf32(sc[j], al, bh0, bh1);
                mma_tf32(sc[j], ah, bl0, bl1);
            }
        }

        // ---- scale + role bias + masks, online softmax ----
        float mx0 = -INFINITY, mx1 = -INFINITY;
        #pragma unroll
        for (int j = 0; j < 8; j++) {
            const int c0 = 8 * j + 2 * t4;
            const int rl0 = roleK[c0],     rl1 = roleK[c0 + 1];
            const int kp0 = kpmK[c0],      kp1 = kpmK[c0 + 1];
            const int ky0 = k0t + c0,      ky1 = ky0 + 1;
            float s00 = sc[j][0] * scale + ((rq0 == rl0) ? delta : 0.f);
            float s01 = sc[j][1] * scale + ((rq0 == rl1) ? delta : 0.f);
            float s10 = sc[j][2] * scale + ((rq1 == rl0) ? delta : 0.f);
            float s11 = sc[j][3] * scale + ((rq1 == rl1) ? delta : 0.f);
            if (ky0 > qg0 || kp0) s00 = -INFINITY;
            if (ky1 > qg0 || kp1) s01 = -INFINITY;
            if (ky0 > qg1 || kp0) s10 = -INFINITY;
            if (ky1 > qg1 || kp1) s11 = -INFINITY;
            sc[j][0] = s00; sc[j][1] = s01; sc[j][2] = s10; sc[j][3] = s11;
            mx0 = fmaxf(mx0, fmaxf(s00, s01));
            mx1 = fmaxf(mx1, fmaxf(s10, s11));
        }
        mx0 = fmaxf(mx0, __shfl_xor_sync(FULL, mx0, 1));
        mx0 = fmaxf(mx0, __shfl_xor_sync(FULL, mx0, 2));
        mx1 = fmaxf(mx1, __shfl_xor_sync(FULL, mx1, 1));
        mx1 = fmaxf(mx1, __shfl_xor_sync(FULL, mx1, 2));

        const float mn0 = fmaxf(m0, mx0);
        const float mn1 = fmaxf(m1, mx1);
        const bool z0 = (mn0 == -INFINITY);
        const bool z1 = (mn1 == -INFINITY);
        const float alpha0 = z0 ? 1.f : __expf(m0 - mn0);
        const float alpha1 = z1 ? 1.f : __expf(m1 - mn1);
        float ps0 = 0.f, ps1 = 0.f;
        #pragma unroll
        for (int j = 0; j < 8; j++) {
            float p;
            p = z0 ? 0.f : __expf(sc[j][0] - mn0); sc[j][0] = p; ps0 += p;
            p = z0 ? 0.f : __expf(sc[j][1] - mn0); sc[j][1] = p; ps0 += p;
            p = z1 ? 0.f : __expf(sc[j][2] - mn1); sc[j][2] = p; ps1 += p;
            p = z1 ? 0.f : __expf(sc[j][3] - mn1); sc[j][3] = p; ps1 += p;
        }
        ps0 += __shfl_xor_sync(FULL, ps0, 1);
        ps0 += __shfl_xor_sync(FULL, ps0, 2);
        ps1 += __shfl_xor_sync(FULL, ps1, 1);
        ps1 += __shfl_xor_sync(FULL, ps1, 2);
        l0 = l0 * alpha0 + ps0;  m0 = mn0;
        l1 = l1 * alpha1 + ps1;  m1 = mn1;

        #pragma unroll
        for (int n = 0; n < 8; n++) {
            O[n][0] *= alpha0; O[n][1] *= alpha0;
            O[n][2] *= alpha1; O[n][3] *= alpha1;
        }

        // ---- O += P V : per 8-key chunk, exchange P to A-layout ----
        const int srcLo = (lane & ~3) | (t4 >> 1);
        const int srcHi = srcLo + 2;
        #pragma unroll
        for (int c = 0; c < 8; c++) {
            float e0, e1, a0f, a1f, a2f, a3f;
            e0 = __shfl_sync(FULL, sc[c][0], srcLo);
            e1 = __shfl_sync(FULL, sc[c][1], srcLo);
            a0f = (t4 & 1) ? e1 : e0;
            e0 = __shfl_sync(FULL, sc[c][2], srcLo);
            e1 = __shfl_sync(FULL, sc[c][3], srcLo);
            a1f = (t4 & 1) ? e1 : e0;
            e0 = __shfl_sync(FULL, sc[c][0], srcHi);
            e1 = __shfl_sync(FULL, sc[c][1], srcHi);
            a2f = (t4 & 1) ? e1 : e0;
            e0 = __shfl_sync(FULL, sc[c][2], srcHi);
            e1 = __shfl_sync(FULL, sc[c][3], srcHi);
            a3f = (t4 & 1) ? e1 : e0;

            uint32_t ph[4], pl[4];
            float hi, lo;
            tf32split(a0f, hi, lo); ph[0] = __float_as_uint(hi); pl[0] = __float_as_uint(lo);
            tf32split(a1f, hi, lo); ph[1] = __float_as_uint(hi); pl[1] = __float_as_uint(lo);
            tf32split(a2f, hi, lo); ph[2] = __float_as_uint(hi); pl[2] = __float_as_uint(lo);
            tf32split(a3f, hi, lo); ph[3] = __float_as_uint(hi); pl[3] = __float_as_uint(lo);

            const int vr = 8 * c + t4;
            #pragma unroll
            for (int n = 0; n < 8; n++) {
                const int vc = 8 * n + g4;
                uint32_t bh0 = __float_as_uint(Vh[vr * VSTR + vc]);
                uint32_t bh1 = __float_as_uint(Vh[(vr + 4) * VSTR + vc]);
                uint32_t bl0 = __float_as_uint(Vl[vr * VSTR + vc]);
                uint32_t bl1 = __float_as_uint(Vl[(vr + 4) * VSTR + vc]);
                mma_tf32(O[n], ph, bh0, bh1);
                mma_tf32(O[n], pl, bh0, bh1);
                mma_tf32(O[n], ph, bl0, bl1);
            }
        }
    }

    // ---- normalize + store ----
    const float i0 = (l0 > 0.f) ? (1.f / l0) : 0.f;
    const float i1 = (l1 > 0.f) ? (1.f / l1) : 0.f;
    #pragma unroll
    for (int n = 0; n < 8; n++) {
        float2 o0, o1;
        o0.x = O[n][0] * i0; o0.y = O[n][1] * i0;
        o1.x = O[n][2] * i1; o1.y = O[n][3] * i1;
        *(float2*)(g_A + base + (size_t)qg0 * DD + 8 * n + 2 * t4) = o0;
        *(float2*)(g_A + base + (size_t)qg1 * DD + 8 * n + 2 * t4) = o1;
    }
}

// ---------------------------------------------------------------------------
// Launch
// ---------------------------------------------------------------------------
extern "C" void kernel_launch(void* const* d_in, const int* in_sizes, int n_in,
                              void* d_out, int out_size)
{
    const float* x    = (const float*)d_in[0];
    const int*   role = (const int*)d_in[1];
    const int*   kpm_raw = (const int*)d_in[3];
    const float* Wq = (const float*)d_in[4];
    const float* bq = (const float*)d_in[5];
    const float* Wk = (const float*)d_in[6];
    const float* bk = (const float*)d_in[7];
    const float* Wv = (const float*)d_in[8];
    const float* bv = (const float*)d_in[9];
    const float* Wo = (const float*)d_in[10];
    const float* bo = (const float*)d_in[11];
    const float* delta = (const float*)d_in[12];

    float *qb, *kb, *vb, *ab;
    cudaGetSymbolAddress((void**)&qb, g_Q);
    cudaGetSymbolAddress((void**)&kb, g_K);
    cudaGetSymbolAddress((void**)&vb, g_V);
    cudaGetSymbolAddress((void**)&ab, g_A);

    cudaFuncSetAttribute(attn_mma,
                         cudaFuncAttributeMaxDynamicSharedMemorySize, ATT_SMEM);

    normalize_kpm<<<1, 256>>>(kpm_raw);

    dim3 ggrid(1024 / 128, MROWS / 128);   // (8, 32)
    gemm_tf32x3<<<ggrid, 256>>>(x, Wq, bq, qb);
    gemm_tf32x3<<<ggrid, 256>>>(x, Wk, bk, kb);
    gemm_tf32x3<<<ggrid, 256>>>(x, Wv, bv, vb);

    dim3 agrid(LL / 128, HH, BB);          // (16, 16, 2)
    attn_mma<<<agrid, 256, ATT_SMEM>>>(role, delta);

    gemm_tf32x3<<<ggrid, 256>>>(ab, Wo, bo, (float*)d_out);
}

// round 12
// speedup vs baseline: 3.1806x; 1.5778x over previous
#include <cuda_runtime.h>
#include <cuda_bf16.h>
#include <cuda_fp16.h>
#include <math.h>
#include <stdint.h>

#define BB 2
#define LL 2048
#define DD 1024
#define HH 16
#define HDIM 64
#define MROWS (BB*LL)   // 4096

// Scratch (allocation-free per harness rules)
static __device__ float g_Q[MROWS * DD];
static __device__ float g_K[MROWS * DD];
static __device__ float g_V[MROWS * DD];
static __device__ float g_A[MROWS * DD];
static __device__ int   g_kpm[BB * LL];

// ---------------------------------------------------------------------------
// Normalize key_padding_mask regardless of on-disk dtype (validated R9-R11).
// ---------------------------------------------------------------------------
__global__ void normalize_kpm(const int* __restrict__ raw)
{
    __shared__ int ok_int, ok_float;
    int tid = threadIdx.x;
    if (tid == 0) { ok_int = 1; ok_float = 1; }
    __syncthreads();
    for (int i = tid; i < BB * LL; i += blockDim.x) {
        int v = raw[i];
        if (v != 0 && v != 1)          ok_int = 0;
        if (v != 0 && v != 0x3F800000) ok_float = 0;
    }
    __syncthreads();
    const unsigned char* raw8 = (const unsigned char*)raw;
    for (int i = tid; i < BB * LL; i += blockDim.x) {
        int out;
        if (ok_int)        out = raw[i];
        else if (ok_float) out = raw[i] ? 1 : 0;
        else               out = raw8[i] ? 1 : 0;
        g_kpm[i] = out;
    }
}

// ---------------------------------------------------------------------------
// fp16 split helpers: x = hi + lo, both fp16; hi/lo each 11-bit mantissa,
// same residual structure as tf32x3 (~2^-22 per product).
// ---------------------------------------------------------------------------
__device__ __forceinline__ void f16split2(float x, float y, uint32_t& hi, uint32_t& lo)
{
    __half hx = __float2half_rn(x);
    __half hy = __float2half_rn(y);
    __half lx = __float2half_rn(x - __half2float(hx));
    __half ly = __float2half_rn(y - __half2float(hy));
    __half2 h = __halves2half2(hx, hy);
    __half2 l = __halves2half2(lx, ly);
    hi = *reinterpret_cast<uint32_t*>(&h);
    lo = *reinterpret_cast<uint32_t*>(&l);
}

__device__ __forceinline__ void mma_f16(float* c, const uint32_t* a,
                                        uint32_t b0, uint32_t b1)
{
    asm volatile(
        "mma.sync.aligned.m16n8k16.row.col.f32.f16.f16.f32 "
        "{%0,%1,%2,%3}, {%4,%5,%6,%7}, {%8,%9}, {%0,%1,%2,%3};\n"
        : "+f"(c[0]), "+f"(c[1]), "+f"(c[2]), "+f"(c[3])
        : "r"(a[0]), "r"(a[1]), "r"(a[2]), "r"(a[3]), "r"(b0), "r"(b1));
}

// ---------------------------------------------------------------------------
// GEMM (fp16x3, m16n8k16): C[m,n] = sum_k A[m,k]*W[n,k] + bias[n]
// M=4096, N=1024, K=1024. Block 128x128, BK=16, 256 threads (8 warps),
// warp tile 32x64. smem holds packed half2 words [row][k/2], stride 12 words
// (fragment loads conflict-free: (12*g4 + t4) % 32 all distinct).
// LDG for iter i+1 issued before MMA of iter i (latency overlap).
// ---------------------------------------------------------------------------
#define GSTR 12

__global__ __launch_bounds__(256) void gemm_f16x3(const float* __restrict__ A,
                                                  const float* __restrict__ W,
                                                  const float* __restrict__ bias,
                                                  float* __restrict__ C)
{
    const int K = 1024, N = 1024;
    __shared__ uint32_t Ah[128 * GSTR];
    __shared__ uint32_t Al[128 * GSTR];
    __shared__ uint32_t Wh[128 * GSTR];
    __shared__ uint32_t Wl[128 * GSTR];

    const int tid  = threadIdx.x;
    const int lane = tid & 31;
    const int wid  = tid >> 5;
    const int wm   = wid & 3;
    const int wn   = wid >> 2;
    const int row0 = blockIdx.y * 128;
    const int col0 = blockIdx.x * 128;
    const int g4 = lane >> 2;
    const int t4 = lane & 3;

    const int lrow = tid >> 1;          // 0..127
    const int lf   = (tid & 1) * 8;     // float k offset 0 or 8
    const int lwc  = (tid & 1) * 4;     // word col base 0 or 4

    float c[2][8][4];
    #pragma unroll
    for (int mt = 0; mt < 2; mt++)
        #pragma unroll
        for (int nt = 0; nt < 8; nt++)
            #pragma unroll
            for (int e = 0; e < 4; e++) c[mt][nt][e] = 0.f;

    const float* Aptr = A + (size_t)(row0 + lrow) * K + lf;
    const float* Wptr = W + (size_t)(col0 + lrow) * K + lf;

    float4 a0 = *(const float4*)(Aptr);
    float4 a1 = *(const float4*)(Aptr + 4);
    float4 w0 = *(const float4*)(Wptr);
    float4 w1 = *(const float4*)(Wptr + 4);

    for (int k0 = 0; k0 < K; k0 += 16) {
        __syncthreads();   // previous iter's fragment reads done

        {
            uint32_t h0,h1,h2,h3, l0,l1,l2,l3;
            f16split2(a0.x, a0.y, h0, l0); f16split2(a0.z, a0.w, h1, l1);
            f16split2(a1.x, a1.y, h2, l2); f16split2(a1.z, a1.w, h3, l3);
            *(uint4*)&Ah[lrow * GSTR + lwc] = make_uint4(h0, h1, h2, h3);
            *(uint4*)&Al[lrow * GSTR + lwc] = make_uint4(l0, l1, l2, l3);
            f16split2(w0.x, w0.y, h0, l0); f16split2(w0.z, w0.w, h1, l1);
            f16split2(w1.x, w1.y, h2, l2); f16split2(w1.z, w1.w, h3, l3);
            *(uint4*)&Wh[lrow * GSTR + lwc] = make_uint4(h0, h1, h2, h3);
            *(uint4*)&Wl[lrow * GSTR + lwc] = make_uint4(l0, l1, l2, l3);
        }
        __syncthreads();

        if (k0 + 16 < K) {   // prefetch next iter (overlaps MMA below)
            a0 = *(const float4*)(Aptr + k0 + 16);
            a1 = *(const float4*)(Aptr + k0 + 20);
            w0 = *(const float4*)(Wptr + k0 + 16);
            w1 = *(const float4*)(Wptr + k0 + 20);
        }

        uint32_t ah[2][4], al[2][4];
        #pragma unroll
        for (int mt = 0; mt < 2; mt++) {
            const int r = wm * 32 + mt * 16 + g4;
            ah[mt][0] = Ah[r * GSTR + t4];
            ah[mt][1] = Ah[(r + 8) * GSTR + t4];
            ah[mt][2] = Ah[r * GSTR + t4 + 4];
            ah[mt][3] = Ah[(r + 8) * GSTR + t4 + 4];
            al[mt][0] = Al[r * GSTR + t4];
            al[mt][1] = Al[(r + 8) * GSTR + t4];
            al[mt][2] = Al[r * GSTR + t4 + 4];
            al[mt][3] = Al[(r + 8) * GSTR + t4 + 4];
        }
        #pragma unroll
        for (int nt = 0; nt < 8; nt++) {
            const int cc = wn * 64 + nt * 8 + g4;
            uint32_t bh0 = Wh[cc * GSTR + t4];
            uint32_t bh1 = Wh[cc * GSTR + t4 + 4];
            uint32_t bl0 = Wl[cc * GSTR + t4];
            uint32_t bl1 = Wl[cc * GSTR + t4 + 4];
            #pragma unroll
            for (int mt = 0; mt < 2; mt++) {
                mma_f16(c[mt][nt], ah[mt], bh0, bh1);   // hi*hi
                mma_f16(c[mt][nt], al[mt], bh0, bh1);   // lo*hi
                mma_f16(c[mt][nt], ah[mt], bl0, bl1);   // hi*lo
            }
        }
    }

    #pragma unroll
    for (int mt = 0; mt < 2; mt++) {
        #pragma unroll
        for (int nt = 0; nt < 8; nt++) {
            int r  = row0 + wm * 32 + mt * 16 + g4;
            int cc = col0 + wn * 64 + nt * 8 + t4 * 2;
            float b0v = bias[cc], b1v = bias[cc + 1];
            C[(size_t)r * N + cc]           = c[mt][nt][0] + b0v;
            C[(size_t)r * N + cc + 1]       = c[mt][nt][1] + b1v;
            C[(size_t)(r + 8) * N + cc]     = c[mt][nt][2] + b0v;
            C[(size_t)(r + 8) * N + cc + 1] = c[mt][nt][3] + b1v;
        }
    }
}

// ---------------------------------------------------------------------------
// Tensor-core flash attention (fp16x3, m16n8k16).
// 128q x 64k tiles, 8 warps (16 q rows each). Grid (L/128, H, B).
// The m16n8 C layout (cols 2t4,2t4+1) IS the m16n8k16 A layout pairing, so
// P fragments come straight from S accumulators — no shuffles.
// V stored transposed [hd][key-pairs] so PV B-fragments pack along keys.
// Word strides 36 -> all fragment LDS conflict-free ((4g4+t4)%32 distinct).
// K/V/role/kpm for tile t+1 prefetched into registers during tile t compute.
// ---------------------------------------------------------------------------
#define ASTR 36
#define Q_WORDS  (128 * ASTR)
#define KV_WORDS (64 * ASTR)
#define ATT_WORDS (2 * Q_WORDS + 4 * KV_WORDS + 128)
#define ATT_SMEM  (ATT_WORDS * 4)

__global__ __launch_bounds__(256, 1) void attn_f16(const int* __restrict__ role,
                                                   const float* __restrict__ deltap)
{
    extern __shared__ uint32_t sw[];
    uint32_t* Qh = sw;
    uint32_t* Ql = Qh + Q_WORDS;
    uint32_t* Kh = Ql + Q_WORDS;
    uint32_t* Kl = Kh + KV_WORDS;
    uint32_t* Vh = Kl + KV_WORDS;
    uint32_t* Vl = Vh + KV_WORDS;
    int* roleK = (int*)(Vl + KV_WORDS);
    int* kpmK  = roleK + 64;

    const int tid  = threadIdx.x;
    const int lane = tid & 31;
    const int w    = tid >> 5;
    const int g4   = lane >> 2;
    const int t4   = lane & 3;
    const int qt = blockIdx.x, h = blockIdx.y, b = blockIdx.z;
    const int q0 = qt * 128;
    const float delta = *deltap;
    const float scale = 0.125f;
    const size_t base = ((size_t)b * LL) * DD + (size_t)h * HDIM;
    const unsigned FULL = 0xffffffffu;

    // ---- load + split Q tile (128 x 64 floats -> packed half2 hi/lo) ----
    for (int i = tid; i < 128 * 16; i += 256) {
        int rr = i >> 4, fc = (i & 15) * 4, wc = (i & 15) * 2;
        float4 v = *(const float4*)(g_Q + base + (size_t)(q0 + rr) * DD + fc);
        uint32_t h0, l0, h1, l1;
        f16split2(v.x, v.y, h0, l0);
        f16split2(v.z, v.w, h1, l1);
        *(uint2*)&Qh[rr * ASTR + wc] = make_uint2(h0, h1);
        *(uint2*)&Ql[rr * ASTR + wc] = make_uint2(l0, l1);
    }

    const int r0  = 16 * w + g4;
    const int qg0 = q0 + r0;
    const int qg1 = qg0 + 8;
    const int rq0 = role[b * LL + qg0];
    const int rq1 = role[b * LL + qg1];

    float m0 = -INFINITY, m1 = -INFINITY, l0s = 0.f, l1s = 0.f;
    float O[8][4];
    #pragma unroll
    for (int n = 0; n < 8; n++)
        #pragma unroll
        for (int e = 0; e < 4; e++) O[n][e] = 0.f;

    // K prefetch mapping: idx = tid + 256p -> row (tid>>4)+16p, float col (tid&15)*4
    const int krow = tid >> 4;
    const int kfc  = (tid & 15) * 4;
    const int kwc  = (tid & 15) * 2;
    // V prefetch mapping: key-pair r = tid&31, hd group c = (tid>>5) + 8*it
    const int vr = tid & 31;
    const int vc0 = tid >> 5;

    const int ntiles = 2 * qt + 2;

    // ---- prefetch tile 0 ----
    float4 kpre[4], vpre[4];
    int rpre = 0, kppre = 0;
    {
        const int k0t = 0;
        #pragma unroll
        for (int p = 0; p < 4; p++)
            kpre[p] = *(const float4*)(g_K + base + (size_t)(k0t + krow + 16 * p) * DD + kfc);
        #pragma unroll
        for (int it = 0; it < 2; it++) {
            const int c = vc0 + 8 * it;
            vpre[2 * it]     = *(const float4*)(g_V + base + (size_t)(k0t + 2 * vr) * DD + 4 * c);
            vpre[2 * it + 1] = *(const float4*)(g_V + base + (size_t)(k0t + 2 * vr + 1) * DD + 4 * c);
        }
        if (tid < 64) { rpre = role[b * LL + k0t + tid]; kppre = g_kpm[b * LL + k0t + tid]; }
    }

    for (int t = 0; t < ntiles; t++) {
        const int k0t = t * 64;
        __syncthreads();   // previous tile's reads done (Q visible at t==0)

        // ---- store K tile (packed along hd) ----
        #pragma unroll
        for (int p = 0; p < 4; p++) {
            const int rr = krow + 16 * p;
            uint32_t h0, l0, h1, l1;
            f16split2(kpre[p].x, kpre[p].y, h0, l0);
            f16split2(kpre[p].z, kpre[p].w, h1, l1);
            *(uint2*)&Kh[rr * ASTR + kwc] = make_uint2(h0, h1);
            *(uint2*)&Kl[rr * ASTR + kwc] = make_uint2(l0, l1);
        }
        // ---- store V transposed (packed along keys) ----
        #pragma unroll
        for (int it = 0; it < 2; it++) {
            const int c = vc0 + 8 * it;
            const float* v0 = (const float*)&vpre[2 * it];
            const float* v1 = (const float*)&vpre[2 * it + 1];
            #pragma unroll
            for (int i = 0; i < 4; i++) {
                uint32_t hw, lw;
                f16split2(v0[i], v1[i], hw, lw);
                Vh[(4 * c + i) * ASTR + vr] = hw;
                Vl[(4 * c + i) * ASTR + vr] = lw;
            }
        }
        if (tid < 64) { roleK[tid] = rpre; kpmK[tid] = kppre; }
        __syncthreads();

        // ---- prefetch tile t+1 (overlaps compute below) ----
        if (t + 1 < ntiles) {
            const int kn = k0t + 64;
            #pragma unroll
            for (int p = 0; p < 4; p++)
                kpre[p] = *(const float4*)(g_K + base + (size_t)(kn + krow + 16 * p) * DD + kfc);
            #pragma unroll
            for (int it = 0; it < 2; it++) {
                const int c = vc0 + 8 * it;
                vpre[2 * it]     = *(const float4*)(g_V + base + (size_t)(kn + 2 * vr) * DD + 4 * c);
                vpre[2 * it + 1] = *(const float4*)(g_V + base + (size_t)(kn + 2 * vr + 1) * DD + 4 * c);
            }
            if (tid < 64) { rpre = role[b * LL + kn + tid]; kppre = g_kpm[b * LL + kn + tid]; }
        }

        // ---- S = Q K^T : 4 k-steps (hd 16 each) x 8 key n-tiles x3 ----
        float sc[8][4];
        #pragma unroll
        for (int j = 0; j < 8; j++)
            #pragma unroll
            for (int e = 0; e < 4; e++) sc[j][e] = 0.f;

        #pragma unroll
        for (int ks = 0; ks < 4; ks++) {
            const int kc = 8 * ks + t4;
            uint32_t ah[4], al[4];
            ah[0] = Qh[r0 * ASTR + kc];
            ah[1] = Qh[(r0 + 8) * ASTR + kc];
            ah[2] = Qh[r0 * ASTR + kc + 4];
            ah[3] = Qh[(r0 + 8) * ASTR + kc + 4];
            al[0] = Ql[r0 * ASTR + kc];
            al[1] = Ql[(r0 + 8) * ASTR + kc];
            al[2] = Ql[r0 * ASTR + kc + 4];
            al[3] = Ql[(r0 + 8) * ASTR + kc + 4];
            #pragma unroll
            for (int j = 0; j < 8; j++) {
                const int kr = 8 * j + g4;
                uint32_t bh0 = Kh[kr * ASTR + kc];
                uint32_t bh1 = Kh[kr * ASTR + kc + 4];
                uint32_t bl0 = Kl[kr * ASTR + kc];
                uint32_t bl1 = Kl[kr * ASTR + kc + 4];
                mma_f16(sc[j], ah, bh0, bh1);
                mma_f16(sc[j], al, bh0, bh1);
                mma_f16(sc[j], ah, bl0, bl1);
            }
        }

        // ---- scale + role bias + masks, online softmax ----
        float mx0 = -INFINITY, mx1 = -INFINITY;
        #pragma unroll
        for (int j = 0; j < 8; j++) {
            const int c0 = 8 * j + 2 * t4;
            const int rl0 = roleK[c0], rl1 = roleK[c0 + 1];
            const int kp0 = kpmK[c0],  kp1 = kpmK[c0 + 1];
            const int ky0 = k0t + c0,  ky1 = ky0 + 1;
            float s00 = sc[j][0] * scale + ((rq0 == rl0) ? delta : 0.f);
            float s01 = sc[j][1] * scale + ((rq0 == rl1) ? delta : 0.f);
            float s10 = sc[j][2] * scale + ((rq1 == rl0) ? delta : 0.f);
            float s11 = sc[j][3] * scale + ((rq1 == rl1) ? delta : 0.f);
            if (ky0 > qg0 || kp0) s00 = -INFINITY;
            if (ky1 > qg0 || kp1) s01 = -INFINITY;
            if (ky0 > qg1 || kp0) s10 = -INFINITY;
            if (ky1 > qg1 || kp1) s11 = -INFINITY;
            sc[j][0] = s00; sc[j][1] = s01; sc[j][2] = s10; sc[j][3] = s11;
            mx0 = fmaxf(mx0, fmaxf(s00, s01));
            mx1 = fmaxf(mx1, fmaxf(s10, s11));
        }
        mx0 = fmaxf(mx0, __shfl_xor_sync(FULL, mx0, 1));
        mx0 = fmaxf(mx0, __shfl_xor_sync(FULL, mx0, 2));
        mx1 = fmaxf(mx1, __shfl_xor_sync(FULL, mx1, 1));
        mx1 = fmaxf(mx1, __shfl_xor_sync(FULL, mx1, 2));

        const float mn0 = fmaxf(m0, mx0);
        const float mn1 = fmaxf(m1, mx1);
        const bool z0 = (mn0 == -INFINITY);
        const bool z1 = (mn1 == -INFINITY);
        const float alpha0 = z0 ? 1.f : __expf(m0 - mn0);
        const float alpha1 = z1 ? 1.f : __expf(m1 - mn1);
        float ps0 = 0.f, ps1 = 0.f;
        #pragma unroll
        for (int j = 0; j < 8; j++) {
            float p;
            p = z0 ? 0.f : __expf(sc[j][0] - mn0); sc[j][0] = p; ps0 += p;
            p = z0 ? 0.f : __expf(sc[j][1] - mn0); sc[j][1] = p; ps0 += p;
            p = z1 ? 0.f : __expf(sc[j][2] - mn1); sc[j][2] = p; ps1 += p;
            p = z1 ? 0.f : __expf(sc[j][3] - mn1); sc[j][3] = p; ps1 += p;
        }
        ps0 += __shfl_xor_sync(FULL, ps0, 1);
        ps0 += __shfl_xor_sync(FULL, ps0, 2);
        ps1 += __shfl_xor_sync(FULL, ps1, 1);
        ps1 += __shfl_xor_sync(FULL, ps1, 2);
        l0s = l0s * alpha0 + ps0;  m0 = mn0;
        l1s = l1s * alpha1 + ps1;  m1 = mn1;

        #pragma unroll
        for (int n = 0; n < 8; n++) {
            O[n][0] *= alpha0; O[n][1] *= alpha0;
            O[n][2] *= alpha1; O[n][3] *= alpha1;
        }

        // ---- O += P V : P fragments directly from S accumulators ----
        #pragma unroll
        for (int c = 0; c < 4; c++) {
            uint32_t ph[4], pl[4];
            f16split2(sc[2 * c][0],     sc[2 * c][1],     ph[0], pl[0]);
            f16split2(sc[2 * c][2],     sc[2 * c][3],     ph[1], pl[1]);
            f16split2(sc[2 * c + 1][0], sc[2 * c + 1][1], ph[2], pl[2]);
            f16split2(sc[2 * c + 1][2], sc[2 * c + 1][3], ph[3], pl[3]);
            #pragma unroll
            for (int n = 0; n < 8; n++) {
                const int vcc = 8 * n + g4;
                uint32_t bh0 = Vh[vcc * ASTR + 8 * c + t4];
                uint32_t bh1 = Vh[vcc * ASTR + 8 * c + t4 + 4];
                uint32_t bl0 = Vl[vcc * ASTR + 8 * c + t4];
                uint32_t bl1 = Vl[vcc * ASTR + 8 * c + t4 + 4];
                mma_f16(O[n], ph, bh0, bh1);
                mma_f16(O[n], pl, bh0, bh1);
                mma_f16(O[n], ph, bl0, bl1);
            }
        }
    }

    // ---- normalize + store ----
    const float i0 = (l0s > 0.f) ? (1.f / l0s) : 0.f;
    const float i1 = (l1s > 0.f) ? (1.f / l1s) : 0.f;
    #pragma unroll
    for (int n = 0; n < 8; n++) {
        float2 o0, o1;
        o0.x = O[n][0] * i0; o0.y = O[n][1] * i0;
        o1.x = O[n][2] * i1; o1.y = O[n][3] * i1;
        *(float2*)(g_A + base + (size_t)qg0 * DD + 8 * n + 2 * t4) = o0;
        *(float2*)(g_A + base + (size_t)qg1 * DD + 8 * n + 2 * t4) = o1;
    }
}

// ---------------------------------------------------------------------------
// Launch
// ---------------------------------------------------------------------------
extern "C" void kernel_launch(void* const* d_in, const int* in_sizes, int n_in,
                              void* d_out, int out_size)
{
    const float* x    = (const float*)d_in[0];
    const int*   role = (const int*)d_in[1];
    const int*   kpm_raw = (const int*)d_in[3];
    const float* Wq = (const float*)d_in[4];
    const float* bq = (const float*)d_in[5];
    const float* Wk = (const float*)d_in[6];
    const float* bk = (const float*)d_in[7];
    const float* Wv = (const float*)d_in[8];
    const float* bv = (const float*)d_in[9];
    const float* Wo = (const float*)d_in[10];
    const float* bo = (const float*)d_in[11];
    const float* delta = (const float*)d_in[12];

    float *qb, *kb, *vb, *ab;
    cudaGetSymbolAddress((void**)&qb, g_Q);
    cudaGetSymbolAddress((void**)&kb, g_K);
    cudaGetSymbolAddress((void**)&vb, g_V);
    cudaGetSymbolAddress((void**)&ab, g_A);

    cudaFuncSetAttribute(attn_f16,
                         cudaFuncAttributeMaxDynamicSharedMemorySize, ATT_SMEM);

    normalize_kpm<<<1, 256>>>(kpm_raw);

    dim3 ggrid(1024 / 128, MROWS / 128);   // (8, 32)
    gemm_f16x3<<<ggrid, 256>>>(x, Wq, bq, qb);
    gemm_f16x3<<<ggrid, 256>>>(x, Wk, bk, kb);
    gemm_f16x3<<<ggrid, 256>>>(x, Wv, bv, vb);

    dim3 agrid(LL / 128, HH, BB);          // (16, 16, 2)
    attn_f16<<<agrid, 256, ATT_SMEM>>>(role, delta);

    gemm_f16x3<<<ggrid, 256>>>(ab, Wo, bo, (float*)d_out);
}

// round 13
// speedup vs baseline: 3.2510x; 1.0221x over previous
#include <cuda_runtime.h>
#include <cuda_bf16.h>
#include <cuda_fp16.h>
#include <math.h>
#include <stdint.h>

#define BB 2
#define LL 2048
#define DD 1024
#define HH 16
#define HDIM 64
#define MROWS (BB*LL)   // 4096

// Scratch (allocation-free per harness rules)
static __device__ float g_Q[MROWS * DD];
static __device__ float g_K[MROWS * DD];
static __device__ float g_V[MROWS * DD];
static __device__ float g_A[MROWS * DD];
static __device__ int   g_kpm[BB * LL];

// ---------------------------------------------------------------------------
// Normalize key_padding_mask regardless of on-disk dtype (validated R9-R12).
// ---------------------------------------------------------------------------
__global__ void normalize_kpm(const int* __restrict__ raw)
{
    __shared__ int ok_int, ok_float;
    int tid = threadIdx.x;
    if (tid == 0) { ok_int = 1; ok_float = 1; }
    __syncthreads();
    for (int i = tid; i < BB * LL; i += blockDim.x) {
        int v = raw[i];
        if (v != 0 && v != 1)          ok_int = 0;
        if (v != 0 && v != 0x3F800000) ok_float = 0;
    }
    __syncthreads();
    const unsigned char* raw8 = (const unsigned char*)raw;
    for (int i = tid; i < BB * LL; i += blockDim.x) {
        int out;
        if (ok_int)        out = raw[i];
        else if (ok_float) out = raw[i] ? 1 : 0;
        else               out = raw8[i] ? 1 : 0;
        g_kpm[i] = out;
    }
}

// ---------------------------------------------------------------------------
// fp16 split helpers: x = hi + lo, both fp16 (11-bit mantissa each;
// residual structure ~2^-22 per product, like tf32x3).
// ---------------------------------------------------------------------------
__device__ __forceinline__ void f16split2(float x, float y, uint32_t& hi, uint32_t& lo)
{
    __half hx = __float2half_rn(x);
    __half hy = __float2half_rn(y);
    __half lx = __float2half_rn(x - __half2float(hx));
    __half ly = __float2half_rn(y - __half2float(hy));
    __half2 h = __halves2half2(hx, hy);
    __half2 l = __halves2half2(lx, ly);
    hi = *reinterpret_cast<uint32_t*>(&h);
    lo = *reinterpret_cast<uint32_t*>(&l);
}

__device__ __forceinline__ void mma_f16(float* c, const uint32_t* a,
                                        uint32_t b0, uint32_t b1)
{
    asm volatile(
        "mma.sync.aligned.m16n8k16.row.col.f32.f16.f16.f32 "
        "{%0,%1,%2,%3}, {%4,%5,%6,%7}, {%8,%9}, {%0,%1,%2,%3};\n"
        : "+f"(c[0]), "+f"(c[1]), "+f"(c[2]), "+f"(c[3])
        : "r"(a[0]), "r"(a[1]), "r"(a[2]), "r"(a[3]), "r"(b0), "r"(b1));
}

// ---------------------------------------------------------------------------
// GEMM (fp16x3, m16n8k16), 2-stage smem double buffer.
// C[m,n] = sum_k A[m,k]*W[n,k] + bias[n].  M=4096, N=1024, K=1024.
// Block 128x128, BK=16, 256 threads (8 warps), warp tile 32x64.
// Per iter: LDG(next) -> LDS+MMA(stage s) -> split/STS(stage s^1) -> 1 sync.
// ---------------------------------------------------------------------------
#define GSTR 12
#define GSTAGE (128 * GSTR)

__global__ __launch_bounds__(256) void gemm_f16x3(const float* __restrict__ A,
                                                  const float* __restrict__ W,
                                                  const float* __restrict__ bias,
                                                  float* __restrict__ C)
{
    const int K = 1024, N = 1024;
    __shared__ uint32_t Ah[2 * GSTAGE];
    __shared__ uint32_t Al[2 * GSTAGE];
    __shared__ uint32_t Wh[2 * GSTAGE];
    __shared__ uint32_t Wl[2 * GSTAGE];

    const int tid  = threadIdx.x;
    const int lane = tid & 31;
    const int wid  = tid >> 5;
    const int wm   = wid & 3;
    const int wn   = wid >> 2;
    const int row0 = blockIdx.y * 128;
    const int col0 = blockIdx.x * 128;
    const int g4 = lane >> 2;
    const int t4 = lane & 3;

    const int lrow = tid >> 1;          // 0..127
    const int lf   = (tid & 1) * 8;     // float k offset 0 or 8
    const int lwc  = (tid & 1) * 4;     // word col base 0 or 4

    float c[2][8][4];
    #pragma unroll
    for (int mt = 0; mt < 2; mt++)
        #pragma unroll
        for (int nt = 0; nt < 8; nt++)
            #pragma unroll
            for (int e = 0; e < 4; e++) c[mt][nt][e] = 0.f;

    const float* Aptr = A + (size_t)(row0 + lrow) * K + lf;
    const float* Wptr = W + (size_t)(col0 + lrow) * K + lf;

    // ---- prologue: iter 0 into stage 0 ----
    float4 a0 = *(const float4*)(Aptr);
    float4 a1 = *(const float4*)(Aptr + 4);
    float4 w0 = *(const float4*)(Wptr);
    float4 w1 = *(const float4*)(Wptr + 4);
    {
        uint32_t h0,h1,h2,h3, l0,l1,l2,l3;
        f16split2(a0.x, a0.y, h0, l0); f16split2(a0.z, a0.w, h1, l1);
        f16split2(a1.x, a1.y, h2, l2); f16split2(a1.z, a1.w, h3, l3);
        *(uint4*)&Ah[lrow * GSTR + lwc] = make_uint4(h0, h1, h2, h3);
        *(uint4*)&Al[lrow * GSTR + lwc] = make_uint4(l0, l1, l2, l3);
        f16split2(w0.x, w0.y, h0, l0); f16split2(w0.z, w0.w, h1, l1);
        f16split2(w1.x, w1.y, h2, l2); f16split2(w1.z, w1.w, h3, l3);
        *(uint4*)&Wh[lrow * GSTR + lwc] = make_uint4(h0, h1, h2, h3);
        *(uint4*)&Wl[lrow * GSTR + lwc] = make_uint4(l0, l1, l2, l3);
    }
    __syncthreads();

    for (int k0 = 0; k0 < K; k0 += 16) {
        const int so = ((k0 >> 4) & 1) * GSTAGE;          // read stage
        const int sn = (((k0 >> 4) + 1) & 1) * GSTAGE;    // write stage
        const bool more = (k0 + 16 < K);

        if (more) {   // LDG next iter — latency covered by MMAs below
            a0 = *(const float4*)(Aptr + k0 + 16);
            a1 = *(const float4*)(Aptr + k0 + 20);
            w0 = *(const float4*)(Wptr + k0 + 16);
            w1 = *(const float4*)(Wptr + k0 + 20);
        }

        uint32_t ah[2][4], al[2][4];
        #pragma unroll
        for (int mt = 0; mt < 2; mt++) {
            const int r = wm * 32 + mt * 16 + g4;
            ah[mt][0] = Ah[so + r * GSTR + t4];
            ah[mt][1] = Ah[so + (r + 8) * GSTR + t4];
            ah[mt][2] = Ah[so + r * GSTR + t4 + 4];
            ah[mt][3] = Ah[so + (r + 8) * GSTR + t4 + 4];
            al[mt][0] = Al[so + r * GSTR + t4];
            al[mt][1] = Al[so + (r + 8) * GSTR + t4];
            al[mt][2] = Al[so + r * GSTR + t4 + 4];
            al[mt][3] = Al[so + (r + 8) * GSTR + t4 + 4];
        }
        #pragma unroll
        for (int nt = 0; nt < 8; nt++) {
            const int cc = wn * 64 + nt * 8 + g4;
            uint32_t bh0 = Wh[so + cc * GSTR + t4];
            uint32_t bh1 = Wh[so + cc * GSTR + t4 + 4];
            uint32_t bl0 = Wl[so + cc * GSTR + t4];
            uint32_t bl1 = Wl[so + cc * GSTR + t4 + 4];
            #pragma unroll
            for (int mt = 0; mt < 2; mt++) {
                mma_f16(c[mt][nt], ah[mt], bh0, bh1);   // hi*hi
                mma_f16(c[mt][nt], al[mt], bh0, bh1);   // lo*hi
                mma_f16(c[mt][nt], ah[mt], bl0, bl1);   // hi*lo
            }
        }

        if (more) {   // split + store into other stage
            uint32_t h0,h1,h2,h3, l0,l1,l2,l3;
            f16split2(a0.x, a0.y, h0, l0); f16split2(a0.z, a0.w, h1, l1);
            f16split2(a1.x, a1.y, h2, l2); f16split2(a1.z, a1.w, h3, l3);
            *(uint4*)&Ah[sn + lrow * GSTR + lwc] = make_uint4(h0, h1, h2, h3);
            *(uint4*)&Al[sn + lrow * GSTR + lwc] = make_uint4(l0, l1, l2, l3);
            f16split2(w0.x, w0.y, h0, l0); f16split2(w0.z, w0.w, h1, l1);
            f16split2(w1.x, w1.y, h2, l2); f16split2(w1.z, w1.w, h3, l3);
            *(uint4*)&Wh[sn + lrow * GSTR + lwc] = make_uint4(h0, h1, h2, h3);
            *(uint4*)&Wl[sn + lrow * GSTR + lwc] = make_uint4(l0, l1, l2, l3);
        }
        __syncthreads();
    }

    #pragma unroll
    for (int mt = 0; mt < 2; mt++) {
        #pragma unroll
        for (int nt = 0; nt < 8; nt++) {
            int r  = row0 + wm * 32 + mt * 16 + g4;
            int cc = col0 + wn * 64 + nt * 8 + t4 * 2;
            float b0v = bias[cc], b1v = bias[cc + 1];
            C[(size_t)r * N + cc]           = c[mt][nt][0] + b0v;
            C[(size_t)r * N + cc + 1]       = c[mt][nt][1] + b1v;
            C[(size_t)(r + 8) * N + cc]     = c[mt][nt][2] + b0v;
            C[(size_t)(r + 8) * N + cc + 1] = c[mt][nt][3] + b1v;
        }
    }
}

// ---------------------------------------------------------------------------
// Tensor-core flash attention (fp16x3, m16n8k16), 2-stage K/V double buffer.
// 128q x 64k tiles, 8 warps (16 q rows each). Grid (L/128, H, B).
// m16n8 C layout == m16n8k16 A layout pairing -> P from S regs, no shuffles.
// V stored transposed [hd][key-pairs]. Word stride 36: conflict-free.
// Per tile: LDG(next) -> MMA+softmax(stage s) -> split/STS(stage s^1) -> 1 sync.
// ---------------------------------------------------------------------------
#define ASTR 36
#define Q_WORDS  (128 * ASTR)
#define KV_WORDS (64 * ASTR)
#define KVSTAGE  (4 * KV_WORDS + 128)
#define ATT_WORDS (2 * Q_WORDS + 2 * KVSTAGE)
#define ATT_SMEM  (ATT_WORDS * 4)

__global__ __launch_bounds__(256, 1) void attn_f16(const int* __restrict__ role,
                                                   const float* __restrict__ deltap)
{
    extern __shared__ uint32_t sw[];
    uint32_t* Qh = sw;
    uint32_t* Ql = Qh + Q_WORDS;
    uint32_t* kvb = Ql + Q_WORDS;   // 2 stages: [Kh | Kl | Vh | Vl | role | kpm]

    const int tid  = threadIdx.x;
    const int lane = tid & 31;
    const int w    = tid >> 5;
    const int g4   = lane >> 2;
    const int t4   = lane & 3;
    const int qt = blockIdx.x, h = blockIdx.y, b = blockIdx.z;
    const int q0 = qt * 128;
    const float delta = *deltap;
    const float scale = 0.125f;
    const size_t base = ((size_t)b * LL) * DD + (size_t)h * HDIM;
    const unsigned FULL = 0xffffffffu;

    // ---- load + split Q tile (written once, read all iterations) ----
    for (int i = tid; i < 128 * 16; i += 256) {
        int rr = i >> 4, fc = (i & 15) * 4, wc = (i & 15) * 2;
        float4 v = *(const float4*)(g_Q + base + (size_t)(q0 + rr) * DD + fc);
        uint32_t h0, l0, h1, l1;
        f16split2(v.x, v.y, h0, l0);
        f16split2(v.z, v.w, h1, l1);
        *(uint2*)&Qh[rr * ASTR + wc] = make_uint2(h0, h1);
        *(uint2*)&Ql[rr * ASTR + wc] = make_uint2(l0, l1);
    }

    const int r0  = 16 * w + g4;
    const int qg0 = q0 + r0;
    const int qg1 = qg0 + 8;
    const int rq0 = role[b * LL + qg0];
    const int rq1 = role[b * LL + qg1];

    float m0 = -INFINITY, m1 = -INFINITY, l0s = 0.f, l1s = 0.f;
    float O[8][4];
    #pragma unroll
    for (int n = 0; n < 8; n++)
        #pragma unroll
        for (int e = 0; e < 4; e++) O[n][e] = 0.f;

    // K prefetch mapping: row (tid>>4)+16p, float col (tid&15)*4
    const int krow = tid >> 4;
    const int kfc  = (tid & 15) * 4;
    const int kwc  = (tid & 15) * 2;
    // V prefetch mapping: key-pair r = tid&31, hd group c = (tid>>5)+8*it
    const int vr  = tid & 31;
    const int vc0 = tid >> 5;

    const int ntiles = 2 * qt + 2;

    float4 kpre[4], vpre[4];
    int rpre = 0, kppre = 0;

    // ---- prologue: tile 0 -> stage 0 ----
    #pragma unroll
    for (int p = 0; p < 4; p++)
        kpre[p] = *(const float4*)(g_K + base + (size_t)(krow + 16 * p) * DD + kfc);
    #pragma unroll
    for (int it = 0; it < 2; it++) {
        const int c = vc0 + 8 * it;
        vpre[2 * it]     = *(const float4*)(g_V + base + (size_t)(2 * vr) * DD + 4 * c);
        vpre[2 * it + 1] = *(const float4*)(g_V + base + (size_t)(2 * vr + 1) * DD + 4 * c);
    }
    if (tid < 64) { rpre = role[b * LL + tid]; kppre = g_kpm[b * LL + tid]; }
    {
        uint32_t* Kh0 = kvb;
        uint32_t* Kl0 = Kh0 + KV_WORDS;
        uint32_t* Vh0 = Kl0 + KV_WORDS;
        uint32_t* Vl0 = Vh0 + KV_WORDS;
        int* roleK0 = (int*)(Vl0 + KV_WORDS);
        int* kpmK0  = roleK0 + 64;
        #pragma unroll
        for (int p = 0; p < 4; p++) {
            const int rr = krow + 16 * p;
            uint32_t h0, l0, h1, l1;
            f16split2(kpre[p].x, kpre[p].y, h0, l0);
            f16split2(kpre[p].z, kpre[p].w, h1, l1);
            *(uint2*)&Kh0[rr * ASTR + kwc] = make_uint2(h0, h1);
            *(uint2*)&Kl0[rr * ASTR + kwc] = make_uint2(l0, l1);
        }
        #pragma unroll
        for (int it = 0; it < 2; it++) {
            const int c = vc0 + 8 * it;
            const float* v0 = (const float*)&vpre[2 * it];
            const float* v1 = (const float*)&vpre[2 * it + 1];
            #pragma unroll
            for (int i = 0; i < 4; i++) {
                uint32_t hw, lw;
                f16split2(v0[i], v1[i], hw, lw);
                Vh0[(4 * c + i) * ASTR + vr] = hw;
                Vl0[(4 * c + i) * ASTR + vr] = lw;
            }
        }
        if (tid < 64) { roleK0[tid] = rpre; kpmK0[tid] = kppre; }
    }
    __syncthreads();

    for (int t = 0; t < ntiles; t++) {
        const int k0t = t * 64;
        const bool more = (t + 1 < ntiles);

        uint32_t* Kh = kvb + (t & 1) * KVSTAGE;
        uint32_t* Kl = Kh + KV_WORDS;
        uint32_t* Vh = Kl + KV_WORDS;
        uint32_t* Vl = Vh + KV_WORDS;
        const int* roleK = (const int*)(Vl + KV_WORDS);
        const int* kpmK  = roleK + 64;

        // ---- LDG next tile (latency covered by compute below) ----
        if (more) {
            const int kn = k0t + 64;
            #pragma unroll
            for (int p = 0; p < 4; p++)
                kpre[p] = *(const float4*)(g_K + base + (size_t)(kn + krow + 16 * p) * DD + kfc);
            #pragma unroll
            for (int it = 0; it < 2; it++) {
                const int c = vc0 + 8 * it;
                vpre[2 * it]     = *(const float4*)(g_V + base + (size_t)(kn + 2 * vr) * DD + 4 * c);
                vpre[2 * it + 1] = *(const float4*)(g_V + base + (size_t)(kn + 2 * vr + 1) * DD + 4 * c);
            }
            if (tid < 64) { rpre = role[b * LL + kn + tid]; kppre = g_kpm[b * LL + kn + tid]; }
        }

        // ---- S = Q K^T ----
        float sc[8][4];
        #pragma unroll
        for (int j = 0; j < 8; j++)
            #pragma unroll
            for (int e = 0; e < 4; e++) sc[j][e] = 0.f;

        #pragma unroll
        for (int ks = 0; ks < 4; ks++) {
            const int kc = 8 * ks + t4;
            uint32_t ah[4], al[4];
            ah[0] = Qh[r0 * ASTR + kc];
            ah[1] = Qh[(r0 + 8) * ASTR + kc];
            ah[2] = Qh[r0 * ASTR + kc + 4];
            ah[3] = Qh[(r0 + 8) * ASTR + kc + 4];
            al[0] = Ql[r0 * ASTR + kc];
            al[1] = Ql[(r0 + 8) * ASTR + kc];
            al[2] = Ql[r0 * ASTR + kc + 4];
            al[3] = Ql[(r0 + 8) * ASTR + kc + 4];
            #pragma unroll
            for (int j = 0; j < 8; j++) {
                const int kr = 8 * j + g4;
                uint32_t bh0 = Kh[kr * ASTR + kc];
                uint32_t bh1 = Kh[kr * ASTR + kc + 4];
                uint32_t bl0 = Kl[kr * ASTR + kc];
                uint32_t bl1 = Kl[kr * ASTR + kc + 4];
                mma_f16(sc[j], ah, bh0, bh1);
                mma_f16(sc[j], al, bh0, bh1);
                mma_f16(sc[j], ah, bl0, bl1);
            }
        }

        // ---- scale + role bias + masks, online softmax ----
        float mx0 = -INFINITY, mx1 = -INFINITY;
        #pragma unroll
        for (int j = 0; j < 8; j++) {
            const int c0 = 8 * j + 2 * t4;
            const int rl0 = roleK[c0], rl1 = roleK[c0 + 1];
            const int kp0 = kpmK[c0],  kp1 = kpmK[c0 + 1];
            const int ky0 = k0t + c0,  ky1 = ky0 + 1;
            float s00 = sc[j][0] * scale + ((rq0 == rl0) ? delta : 0.f);
            float s01 = sc[j][1] * scale + ((rq0 == rl1) ? delta : 0.f);
            float s10 = sc[j][2] * scale + ((rq1 == rl0) ? delta : 0.f);
            float s11 = sc[j][3] * scale + ((rq1 == rl1) ? delta : 0.f);
            if (ky0 > qg0 || kp0) s00 = -INFINITY;
            if (ky1 > qg0 || kp1) s01 = -INFINITY;
            if (ky0 > qg1 || kp0) s10 = -INFINITY;
            if (ky1 > qg1 || kp1) s11 = -INFINITY;
            sc[j][0] = s00; sc[j][1] = s01; sc[j][2] = s10; sc[j][3] = s11;
            mx0 = fmaxf(mx0, fmaxf(s00, s01));
            mx1 = fmaxf(mx1, fmaxf(s10, s11));
        }
        mx0 = fmaxf(mx0, __shfl_xor_sync(FULL, mx0, 1));
        mx0 = fmaxf(mx0, __shfl_xor_sync(FULL, mx0, 2));
        mx1 = fmaxf(mx1, __shfl_xor_sync(FULL, mx1, 1));
        mx1 = fmaxf(mx1, __shfl_xor_sync(FULL, mx1, 2));

        const float mn0 = fmaxf(m0, mx0);
        const float mn1 = fmaxf(m1, mx1);
        const bool z0 = (mn0 == -INFINITY);
        const bool z1 = (mn1 == -INFINITY);
        const float alpha0 = z0 ? 1.f : __expf(m0 - mn0);
        const float alpha1 = z1 ? 1.f : __expf(m1 - mn1);
        float ps0 = 0.f, ps1 = 0.f;
        #pragma unroll
        for (int j = 0; j < 8; j++) {
            float p;
            p = z0 ? 0.f : __expf(sc[j][0] - mn0); sc[j][0] = p; ps0 += p;
            p = z0 ? 0.f : __expf(sc[j][1] - mn0); sc[j][1] = p; ps0 += p;
            p = z1 ? 0.f : __expf(sc[j][2] - mn1); sc[j][2] = p; ps1 += p;
            p = z1 ? 0.f : __expf(sc[j][3] - mn1); sc[j][3] = p; ps1 += p;
        }
        ps0 += __shfl_xor_sync(FULL, ps0, 1);
        ps0 += __shfl_xor_sync(FULL, ps0, 2);
        ps1 += __shfl_xor_sync(FULL, ps1, 1);
        ps1 += __shfl_xor_sync(FULL, ps1, 2);
        l0s = l0s * alpha0 + ps0;  m0 = mn0;
        l1s = l1s * alpha1 + ps1;  m1 = mn1;

        #pragma unroll
        for (int n = 0; n < 8; n++) {
            O[n][0] *= alpha0; O[n][1] *= alpha0;
            O[n][2] *= alpha1; O[n][3] *= alpha1;
        }

        // ---- O += P V : P fragments directly from S accumulators ----
        #pragma unroll
        for (int c = 0; c < 4; c++) {
            uint32_t ph[4], pl[4];
            f16split2(sc[2 * c][0],     sc[2 * c][1],     ph[0], pl[0]);
            f16split2(sc[2 * c][2],     sc[2 * c][3],     ph[1], pl[1]);
            f16split2(sc[2 * c + 1][0], sc[2 * c + 1][1], ph[2], pl[2]);
            f16split2(sc[2 * c + 1][2], sc[2 * c + 1][3], ph[3], pl[3]);
            #pragma unroll
            for (int n = 0; n < 8; n++) {
                const int vcc = 8 * n + g4;
                uint32_t bh0 = Vh[vcc * ASTR + 8 * c + t4];
                uint32_t bh1 = Vh[vcc * ASTR + 8 * c + t4 + 4];
                uint32_t bl0 = Vl[vcc * ASTR + 8 * c + t4];
                uint32_t bl1 = Vl[vcc * ASTR + 8 * c + t4 + 4];
                mma_f16(O[n], ph, bh0, bh1);
                mma_f16(O[n], pl, bh0, bh1);
                mma_f16(O[n], ph, bl0, bl1);
            }
        }

        // ---- split/store next tile into other stage, then ONE sync ----
        if (more) {
            uint32_t* nKh = kvb + ((t + 1) & 1) * KVSTAGE;
            uint32_t* nKl = nKh + KV_WORDS;
            uint32_t* nVh = nKl + KV_WORDS;
            uint32_t* nVl = nVh + KV_WORDS;
            int* nroleK = (int*)(nVl + KV_WORDS);
            int* nkpmK  = nroleK + 64;
            #pragma unroll
            for (int p = 0; p < 4; p++) {
                const int rr = krow + 16 * p;
                uint32_t h0, l0, h1, l1;
                f16split2(kpre[p].x, kpre[p].y, h0, l0);
                f16split2(kpre[p].z, kpre[p].w, h1, l1);
                *(uint2*)&nKh[rr * ASTR + kwc] = make_uint2(h0, h1);
                *(uint2*)&nKl[rr * ASTR + kwc] = make_uint2(l0, l1);
            }
            #pragma unroll
            for (int it = 0; it < 2; it++) {
                const int c = vc0 + 8 * it;
                const float* v0 = (const float*)&vpre[2 * it];
                const float* v1 = (const float*)&vpre[2 * it + 1];
                #pragma unroll
                for (int i = 0; i < 4; i++) {
                    uint32_t hw, lw;
                    f16split2(v0[i], v1[i], hw, lw);
                    nVh[(4 * c + i) * ASTR + vr] = hw;
                    nVl[(4 * c + i) * ASTR + vr] = lw;
                }
            }
            if (tid < 64) { nroleK[tid] = rpre; nkpmK[tid] = kppre; }
            __syncthreads();
        }
    }

    // ---- normalize + store ----
    const float i0 = (l0s > 0.f) ? (1.f / l0s) : 0.f;
    const float i1 = (l1s > 0.f) ? (1.f / l1s) : 0.f;
    #pragma unroll
    for (int n = 0; n < 8; n++) {
        float2 o0, o1;
        o0.x = O[n][0] * i0; o0.y = O[n][1] * i0;
        o1.x = O[n][2] * i1; o1.y = O[n][3] * i1;
        *(float2*)(g_A + base + (size_t)qg0 * DD + 8 * n + 2 * t4) = o0;
        *(float2*)(g_A + base + (size_t)qg1 * DD + 8 * n + 2 * t4) = o1;
    }
}

// ---------------------------------------------------------------------------
// Launch
// ---------------------------------------------------------------------------
extern "C" void kernel_launch(void* const* d_in, const int* in_sizes, int n_in,
                              void* d_out, int out_size)
{
    const float* x    = (const float*)d_in[0];
    const int*   role = (const int*)d_in[1];
    const int*   kpm_raw = (const int*)d_in[3];
    const float* Wq = (const float*)d_in[4];
    const float* bq = (const float*)d_in[5];
    const float* Wk = (const float*)d_in[6];
    const float* bk = (const float*)d_in[7];
    const float* Wv = (const float*)d_in[8];
    const float* bv = (const float*)d_in[9];
    const float* Wo = (const float*)d_in[10];
    const float* bo = (const float*)d_in[11];
    const float* delta = (const float*)d_in[12];

    float *qb, *kb, *vb, *ab;
    cudaGetSymbolAddress((void**)&qb, g_Q);
    cudaGetSymbolAddress((void**)&kb, g_K);
    cudaGetSymbolAddress((void**)&vb, g_V);
    cudaGetSymbolAddress((void**)&ab, g_A);

    cudaFuncSetAttribute(attn_f16,
                         cudaFuncAttributeMaxDynamicSharedMemorySize, ATT_SMEM);

    normalize_kpm<<<1, 256>>>(kpm_raw);

    dim3 ggrid(1024 / 128, MROWS / 128);   // (8, 32)
    gemm_f16x3<<<ggrid, 256>>>(x, Wq, bq, qb);
    gemm_f16x3<<<ggrid, 256>>>(x, Wk, bk, kb);
    gemm_f16x3<<<ggrid, 256>>>(x, Wv, bv, vb);

    dim3 agrid(LL / 128, HH, BB);          // (16, 16, 2)
    attn_f16<<<agrid, 256, ATT_SMEM>>>(role, delta);

    gemm_f16x3<<<ggrid, 256>>>(ab, Wo, bo, (float*)d_out);
}